// round 8
// baseline (speedup 1.0000x reference)
#include <cuda_runtime.h>
#include <cuda_bf16.h>
#include <math.h>
#include <stdint.h>

#define Bn 16384
#define Dn 512
#define Kn 16384
#define Hn 256
#define Zn 128
#define KGROUPS 4
#define KG_CODES (Kn / KGROUPS)     // 4096
#define KG_TILES (KG_CODES / 128)   // 32

// ---------------- scratch ----------------
__device__ __align__(16) float g_enc[(size_t)Bn * Zn];
__device__ __align__(16) __nv_bfloat16 g_e0[(size_t)Bn * Zn];
__device__ __align__(16) __nv_bfloat16 g_c0[(size_t)Kn * Zn];
__device__ float g_negc2[Kn];
__device__ float g_en2[Bn];
__device__ float g_dn2[Bn];
__device__ float g_Rmax2;
__device__ float g_Nmax2;
__device__ float g_smaxp[(size_t)Bn * KGROUPS];
__device__ float g_cand_val[(size_t)Bn * 192];
__device__ int   g_cand_idx[(size_t)Bn * 192];
__device__ float g_fourth[(size_t)Bn * 64];
__device__ int   g_idx[Bn];
__device__ float g_err[Bn];
__device__ float g_sum;

// ---------------- helpers ----------------
__device__ __forceinline__ uint32_t smem_u32(const void* p) {
    uint32_t a;
    asm("{ .reg .u64 t; cvta.to.shared.u64 t, %1; cvt.u32.u64 %0, t; }" : "=r"(a) : "l"(p));
    return a;
}
__device__ __forceinline__ void ldsm_x4(uint32_t r[4], uint32_t addr) {
    asm volatile("ldmatrix.sync.aligned.m8n8.x4.shared.b16 {%0,%1,%2,%3}, [%4];"
        : "=r"(r[0]), "=r"(r[1]), "=r"(r[2]), "=r"(r[3]) : "r"(addr));
}
__device__ __forceinline__ void mma_bf16(float d[4], const uint32_t a[4], const uint32_t b[2]) {
    asm volatile("mma.sync.aligned.m16n8k16.row.col.f32.bf16.bf16.f32 "
        "{%0,%1,%2,%3}, {%4,%5,%6,%7}, {%8,%9}, {%0,%1,%2,%3};"
        : "+f"(d[0]), "+f"(d[1]), "+f"(d[2]), "+f"(d[3])
        : "r"(a[0]), "r"(a[1]), "r"(a[2]), "r"(a[3]), "r"(b[0]), "r"(b[1]));
}
__device__ __forceinline__ uint32_t pack_bf16(float a, float b) {
    __nv_bfloat162 t = __floats2bfloat162_rn(a, b);
    return *(uint32_t*)&t;
}
__device__ __forceinline__ void cpasync16(uint32_t saddr, const void* g) {
    asm volatile("cp.async.cg.shared.global [%0], [%1], 16;" :: "r"(saddr), "l"(g));
}
#define CP_COMMIT() asm volatile("cp.async.commit_group;" ::: "memory")
#define CP_WAIT1()  asm volatile("cp.async.wait_group 1;" ::: "memory")
#define CP_WAIT0()  asm volatile("cp.async.wait_group 0;" ::: "memory")

// ---------------- encoder ----------------
__global__ void encoder_kernel(const float* __restrict__ X,
                               const float* __restrict__ W1, const float* __restrict__ b1,
                               const float* __restrict__ g1, const float* __restrict__ be1,
                               const float* __restrict__ W2, const float* __restrict__ b2)
{
    extern __shared__ float sm[];
    float* Xs = sm;
    float* Hs = sm + 32 * Dn;
    const int tid = threadIdx.x;
    const int row0 = blockIdx.x * 32;

    {
        const float4* Xg = (const float4*)(X + (size_t)row0 * Dn);
        float4* Xs4 = (float4*)Xs;
        for (int i = tid; i < 32 * Dn / 4; i += 256) Xs4[i] = Xg[i];
    }
    __syncthreads();

    const float4* Xs4 = (const float4*)Xs;
    float acc[32];
#pragma unroll
    for (int r = 0; r < 32; ++r) acc[r] = 0.f;
    const int col = tid;
    for (int d = 0; d < Dn; d += 4) {
        float w0 = W1[(d + 0) * Hn + col];
        float w1 = W1[(d + 1) * Hn + col];
        float w2 = W1[(d + 2) * Hn + col];
        float w3 = W1[(d + 3) * Hn + col];
#pragma unroll
        for (int r = 0; r < 32; ++r) {
            float4 x = Xs4[(r * Dn + d) >> 2];
            acc[r] = fmaf(x.x, w0, acc[r]);
            acc[r] = fmaf(x.y, w1, acc[r]);
            acc[r] = fmaf(x.z, w2, acc[r]);
            acc[r] = fmaf(x.w, w3, acc[r]);
        }
    }
    {
        float bb = b1[col];
#pragma unroll
        for (int r = 0; r < 32; ++r) Hs[r * Hn + col] = acc[r] + bb;
    }
    __syncthreads();

    {
        const int warp = tid >> 5, lane = tid & 31;
        for (int rr = 0; rr < 4; ++rr) {
            int r = warp + rr * 8;
            float s = 0.f, s2 = 0.f;
#pragma unroll
            for (int j = 0; j < 8; ++j) {
                float v = Hs[r * Hn + lane + j * 32];
                s += v; s2 += v * v;
            }
#pragma unroll
            for (int o = 16; o > 0; o >>= 1) {
                s  += __shfl_xor_sync(0xffffffff, s,  o);
                s2 += __shfl_xor_sync(0xffffffff, s2, o);
            }
            float mu  = s * (1.f / Hn);
            float var = s2 * (1.f / Hn) - mu * mu;
            float inv = rsqrtf(var + 1e-5f);
#pragma unroll
            for (int j = 0; j < 8; ++j) {
                int c = lane + j * 32;
                float v = (Hs[r * Hn + c] - mu) * inv * g1[c] + be1[c];
                Hs[r * Hn + c] = 0.5f * v * (1.f + erff(v * 0.70710678118654752f));
            }
        }
    }
    __syncthreads();

    {
        const float4* Hs4 = (const float4*)Hs;
        const int c2 = tid & 127;
        const int rbase = (tid >> 7) * 16;
        float a2[16];
#pragma unroll
        for (int r = 0; r < 16; ++r) a2[r] = 0.f;
        for (int d = 0; d < Hn; d += 4) {
            float w0 = W2[(d + 0) * Zn + c2];
            float w1 = W2[(d + 1) * Zn + c2];
            float w2 = W2[(d + 2) * Zn + c2];
            float w3 = W2[(d + 3) * Zn + c2];
#pragma unroll
            for (int r = 0; r < 16; ++r) {
                float4 h = Hs4[((rbase + r) * Hn + d) >> 2];
                a2[r] = fmaf(h.x, w0, a2[r]);
                a2[r] = fmaf(h.y, w1, a2[r]);
                a2[r] = fmaf(h.z, w2, a2[r]);
                a2[r] = fmaf(h.w, w3, a2[r]);
            }
        }
        float bb = b2[c2];
#pragma unroll
        for (int r = 0; r < 16; ++r)
            g_enc[(size_t)(row0 + rbase + r) * Zn + c2] = a2[r] + bb;
    }
}

// ---------------- per-row e0 + norms ----------------
__global__ void enorm_kernel()
{
    int gw = (blockIdx.x * 256 + threadIdx.x) >> 5;
    int lane = threadIdx.x & 31;
    const float4 e4 = ((const float4*)(g_enc + (size_t)gw * 128))[lane];
    float e0x = __bfloat162float(__float2bfloat16(e4.x));
    float e0y = __bfloat162float(__float2bfloat16(e4.y));
    float e0z = __bfloat162float(__float2bfloat16(e4.z));
    float e0w = __bfloat162float(__float2bfloat16(e4.w));
    ((uint2*)(g_e0 + (size_t)gw * 128))[lane] =
        make_uint2(pack_bf16(e4.x, e4.y), pack_bf16(e4.z, e4.w));
    float en2 = e4.x*e4.x + e4.y*e4.y + e4.z*e4.z + e4.w*e4.w;
    float dx = e4.x - e0x, dy = e4.y - e0y, dz = e4.z - e0z, dw = e4.w - e0w;
    float dn2 = dx*dx + dy*dy + dz*dz + dw*dw;
#pragma unroll
    for (int o = 16; o > 0; o >>= 1) {
        en2 += __shfl_xor_sync(0xffffffff, en2, o);
        dn2 += __shfl_xor_sync(0xffffffff, dn2, o);
    }
    if (lane == 0) { g_en2[gw] = en2; g_dn2[gw] = dn2; }
}

// ---------------- codebook prep ----------------
__global__ void c0split_kernel(const float* __restrict__ C)
{
    int code = (blockIdx.x * 256 + threadIdx.x) >> 5;
    int lane = threadIdx.x & 31;
    const float4 c4 = ((const float4*)(C + (size_t)code * 128))[lane];
    float c0x = __bfloat162float(__float2bfloat16(c4.x));
    float c0y = __bfloat162float(__float2bfloat16(c4.y));
    float c0z = __bfloat162float(__float2bfloat16(c4.z));
    float c0w = __bfloat162float(__float2bfloat16(c4.w));
    ((uint2*)(g_c0 + (size_t)code * 128))[lane] =
        make_uint2(pack_bf16(c4.x, c4.y), pack_bf16(c4.z, c4.w));
    float c2 = c4.x*c4.x + c4.y*c4.y + c4.z*c4.z + c4.w*c4.w;
    float n2 = c0x*c0x + c0y*c0y + c0z*c0z + c0w*c0w;
    float dx = c4.x - c0x, dy = c4.y - c0y, dz = c4.z - c0z, dw = c4.w - c0w;
    float r2 = dx*dx + dy*dy + dz*dz + dw*dw;
#pragma unroll
    for (int o = 16; o > 0; o >>= 1) {
        c2 += __shfl_xor_sync(0xffffffff, c2, o);
        n2 += __shfl_xor_sync(0xffffffff, n2, o);
        r2 += __shfl_xor_sync(0xffffffff, r2, o);
    }
    if (lane == 0) {
        g_negc2[code] = -0.5f * c2;
        atomicMax((int*)&g_Rmax2, __float_as_int(r2));
        atomicMax((int*)&g_Nmax2, __float_as_int(n2));
    }
}

// ---------------- coarse distance: 64-row x 4096-code CTAs, 2/SM ----------------
#define LDK2 136
#define A_BYTES (64 * LDK2 * 2)
#define TILE_BYTES (128 * LDK2 * 2)
#define SB_A 0
#define SB_B0 A_BYTES
#define SB_RED (A_BYTES + 2 * TILE_BYTES)
#define DSM2_TOT (SB_RED + 64 * 16 * 4)

__global__ __launch_bounds__(256, 2) void dist_coarse_kernel()
{
    extern __shared__ char smem[];
    float* redsm = (float*)(smem + SB_RED);

    const int tid  = threadIdx.x;
    const int lane = tid & 31;
    const int wid  = tid >> 5;
    const int warp_m = wid >> 2;
    const int warp_n = wid & 3;
    const int rb = blockIdx.x & 255;
    const int kg = blockIdx.x >> 8;       // 0..3
    const int row0 = rb * 64;
    const int kbase = kg * KG_CODES;

    const uint32_t sbA  = smem_u32(smem) + SB_A;
    const uint32_t sbB0 = smem_u32(smem) + SB_B0;

    for (int i = tid; i < 1024; i += 256) {
        int r = i >> 4, u = i & 15;
        cpasync16(sbA + r * (LDK2 * 2) + u * 16,
                  g_e0 + (size_t)(row0 + r) * 128 + u * 8);
    }
    CP_COMMIT();
    for (int i = tid; i < 2048; i += 256) {
        int r = i >> 4, u = i & 15;
        cpasync16(sbB0 + r * (LDK2 * 2) + u * 16,
                  g_c0 + (size_t)(kbase + r) * 128 + u * 8);
    }
    CP_COMMIT();

    uint32_t a_addr[2];
#pragma unroll
    for (int mi = 0; mi < 2; ++mi)
        a_addr[mi] = sbA + ((warp_m * 32 + mi * 16 + (lane & 15)) * LDK2 + (lane >> 4) * 8) * 2;
    uint32_t b_addr[2];
#pragma unroll
    for (int njp = 0; njp < 2; ++njp)
        b_addr[njp] = sbB0 + ((warp_n * 32 + njp * 16 + (lane & 7) + ((lane >> 4) << 3)) * LDK2
                              + ((lane >> 3) & 1) * 8) * 2;

    float v1[4], v2[4], v3[4], v4[4];
    int   i1[4], i2[4], i3[4];
#pragma unroll
    for (int r = 0; r < 4; ++r) {
        v1[r] = v2[r] = v3[r] = v4[r] = -INFINITY;
        i1[r] = i2[r] = i3[r] = 0;
    }

    const int cq = (lane & 3) * 2;

    for (int t = 0; t < KG_TILES; ++t) {
        const int kt = kbase + t * 128;
        const uint32_t bufo = (uint32_t)(t & 1) * TILE_BYTES;
        if (t < KG_TILES - 1) {
            uint32_t sb = sbB0 + ((t + 1) & 1) * TILE_BYTES;
            const __nv_bfloat16* src = g_c0 + (size_t)(kt + 128) * 128;
            for (int i = tid; i < 2048; i += 256) {
                int r = i >> 4, u = i & 15;
                cpasync16(sb + r * (LDK2 * 2) + u * 16, src + (size_t)r * 128 + u * 8);
            }
            CP_COMMIT();
            CP_WAIT1();
        } else {
            CP_WAIT0();
        }
        __syncthreads();

        // -0.5||c||^2 folded into accumulator init (D = A.B + D)
        float nc[8];
#pragma unroll
        for (int nj = 0; nj < 4; ++nj) {
            nc[nj * 2]     = g_negc2[kt + warp_n * 32 + nj * 8 + cq];
            nc[nj * 2 + 1] = g_negc2[kt + warp_n * 32 + nj * 8 + cq + 1];
        }

        float acc[2][4][4];
#pragma unroll
        for (int mi = 0; mi < 2; ++mi)
#pragma unroll
            for (int nj = 0; nj < 4; ++nj)
#pragma unroll
                for (int k = 0; k < 4; ++k) acc[mi][nj][k] = nc[nj * 2 + (k & 1)];

#pragma unroll
        for (int s = 0; s < 8; ++s) {
            uint32_t af[2][4], bf[2][4];
#pragma unroll
            for (int mi = 0; mi < 2; ++mi) ldsm_x4(af[mi], a_addr[mi] + s * 32);
#pragma unroll
            for (int njp = 0; njp < 2; ++njp) ldsm_x4(bf[njp], b_addr[njp] + bufo + s * 32);
#pragma unroll
            for (int mi = 0; mi < 2; ++mi)
#pragma unroll
                for (int nj = 0; nj < 4; ++nj)
                    mma_bf16(acc[mi][nj], af[mi], bf[nj >> 1] + (nj & 1) * 2);
        }

#pragma unroll
        for (int mi = 0; mi < 2; ++mi) {
#pragma unroll
            for (int h = 0; h < 2; ++h) {
                const int ri = mi * 2 + h;
                float s0 = acc[mi][0][h * 2];
                float s1 = acc[mi][0][h * 2 + 1];
                float s2 = acc[mi][1][h * 2];
                float s3 = acc[mi][1][h * 2 + 1];
                float s4 = acc[mi][2][h * 2];
                float s5 = acc[mi][2][h * 2 + 1];
                float s6 = acc[mi][3][h * 2];
                float s7 = acc[mi][3][h * 2 + 1];
                float m8 = fmaxf(fmaxf(fmaxf(s0, s1), fmaxf(s2, s3)),
                                 fmaxf(fmaxf(s4, s5), fmaxf(s6, s7)));
                if (m8 > v4[ri]) {
                    float sv[8] = {s0, s1, s2, s3, s4, s5, s6, s7};
#pragma unroll
                    for (int j = 0; j < 8; ++j) {
                        float v = sv[j];
                        if (v > v4[ri]) {
                            int idx = kt + warp_n * 32 + (j >> 1) * 8 + cq + (j & 1);
                            if (v > v1[ri]) {
                                v4[ri] = v3[ri]; v3[ri] = v2[ri]; i3[ri] = i2[ri];
                                v2[ri] = v1[ri]; i2[ri] = i1[ri];
                                v1[ri] = v; i1[ri] = idx;
                            } else if (v > v2[ri]) {
                                v4[ri] = v3[ri]; v3[ri] = v2[ri]; i3[ri] = i2[ri];
                                v2[ri] = v; i2[ri] = idx;
                            } else if (v > v3[ri]) {
                                v4[ri] = v3[ri]; v3[ri] = v; i3[ri] = idx;
                            } else {
                                v4[ri] = v;
                            }
                        }
                    }
                }
            }
        }
        __syncthreads();
    }

    // write candidates + v4; per-group smax
    const int slot = warp_n * 4 + (lane & 3);
#pragma unroll
    for (int ri = 0; ri < 4; ++ri) {
        int mi = ri >> 1, h = ri & 1;
        int lrow = warp_m * 32 + mi * 16 + (lane >> 2) + h * 8;
        size_t row = (size_t)(row0 + lrow);
        size_t cb = row * 192 + (size_t)kg * 48;
        g_cand_val[cb + slot * 3]     = v1[ri];
        g_cand_idx[cb + slot * 3]     = i1[ri];
        g_cand_val[cb + slot * 3 + 1] = v2[ri];
        g_cand_idx[cb + slot * 3 + 1] = i2[ri];
        g_cand_val[cb + slot * 3 + 2] = v3[ri];
        g_cand_idx[cb + slot * 3 + 2] = i3[ri];
        g_fourth[row * 64 + kg * 16 + slot] = v4[ri];
        redsm[lrow * 16 + slot] = v1[ri];
    }
    __syncthreads();
    if (tid < 64) {
        float m = redsm[tid * 16];
#pragma unroll
        for (int w = 1; w < 16; ++w) m = fmaxf(m, redsm[tid * 16 + w]);
        g_smaxp[(size_t)(row0 + tid) * KGROUPS + kg] = m;
    }
}

// ---------------- exact rescore (warp per row) ----------------
__global__ void rescore_kernel(const float* __restrict__ CB)
{
    const int r = blockIdx.x * 4 + (threadIdx.x >> 5);
    const int lane = threadIdx.x & 31;

    float smax = g_smaxp[(size_t)r * KGROUPS];
#pragma unroll
    for (int g = 1; g < KGROUPS; ++g)
        smax = fmaxf(smax, g_smaxp[(size_t)r * KGROUPS + g]);

    float delta = sqrtf(g_en2[r]) * sqrtf(g_Rmax2) + sqrtf(g_dn2[r]) * sqrtf(g_Nmax2);
    float thresh = smax - 1.05f * delta - 1e-4f;

    float th = fmaxf(g_fourth[(size_t)r * 64 + lane],
                     g_fourth[(size_t)r * 64 + 32 + lane]);
    bool flag = __ballot_sync(0xffffffff, th >= thresh) != 0;

    const float4 e4 = ((const float4*)(g_enc + (size_t)r * 128))[lane];

    float bs = -INFINITY;
    int bi = 0x7fffffff;

    if (!flag) {
        for (int s = 0; s < 192; ++s) {
            float v = g_cand_val[(size_t)r * 192 + s];
            if (v >= thresh) {
                int idx = g_cand_idx[(size_t)r * 192 + s];
                float4 c4 = ((const float4*)(CB + (size_t)idx * 128))[lane];
                float d = e4.x*c4.x + e4.y*c4.y + e4.z*c4.z + e4.w*c4.w;
#pragma unroll
                for (int o = 16; o > 0; o >>= 1) d += __shfl_xor_sync(0xffffffff, d, o);
                float sx = d + g_negc2[idx];
                if (sx > bs || (sx == bs && idx < bi)) { bs = sx; bi = idx; }
            }
        }
    } else {
        for (int k = 0; k < Kn; ++k) {
            float4 c4 = ((const float4*)(CB + (size_t)k * 128))[lane];
            float d = e4.x*c4.x + e4.y*c4.y + e4.z*c4.z + e4.w*c4.w;
#pragma unroll
            for (int o = 16; o > 0; o >>= 1) d += __shfl_xor_sync(0xffffffff, d, o);
            float sx = d + g_negc2[k];
            if (sx > bs) { bs = sx; bi = k; }
        }
    }
    if (lane == 0) g_idx[r] = bi;
}

// ---------------- decoder ----------------
__global__ void decoder_kernel(const float* __restrict__ C,
                               const float* __restrict__ W3, const float* __restrict__ b3,
                               const float* __restrict__ g2, const float* __restrict__ be2,
                               const float* __restrict__ W4, const float* __restrict__ b4,
                               const float* __restrict__ X)
{
    extern __shared__ float sm[];
    float* Qs = sm;
    float* Hs = sm + 32 * Zn;
    float* ep = Hs + 32 * Hn;
    const int tid = threadIdx.x;
    const int row0 = blockIdx.x * 32;

    for (int i = tid; i < 32 * 32; i += 256) {
        int r = i >> 5, d4 = i & 31;
        int code = g_idx[row0 + r];
        ((float4*)Qs)[r * 32 + d4] = ((const float4*)C)[(size_t)code * 32 + d4];
    }
    __syncthreads();

    {
        const float4* Qs4 = (const float4*)Qs;
        float acc[32];
#pragma unroll
        for (int r = 0; r < 32; ++r) acc[r] = 0.f;
        const int col = tid;
        for (int d = 0; d < Zn; d += 4) {
            float w0 = W3[(d + 0) * Hn + col];
            float w1 = W3[(d + 1) * Hn + col];
            float w2 = W3[(d + 2) * Hn + col];
            float w3 = W3[(d + 3) * Hn + col];
#pragma unroll
            for (int r = 0; r < 32; ++r) {
                float4 q = Qs4[(r * Zn + d) >> 2];
                acc[r] = fmaf(q.x, w0, acc[r]);
                acc[r] = fmaf(q.y, w1, acc[r]);
                acc[r] = fmaf(q.z, w2, acc[r]);
                acc[r] = fmaf(q.w, w3, acc[r]);
            }
        }
        float bb = b3[col];
#pragma unroll
        for (int r = 0; r < 32; ++r) Hs[r * Hn + col] = acc[r] + bb;
    }
    __syncthreads();

    {
        const int warp = tid >> 5, lane = tid & 31;
        for (int rr = 0; rr < 4; ++rr) {
            int r = warp + rr * 8;
            float s = 0.f, s2 = 0.f;
#pragma unroll
            for (int j = 0; j < 8; ++j) {
                float v = Hs[r * Hn + lane + j * 32];
                s += v; s2 += v * v;
            }
#pragma unroll
            for (int o = 16; o > 0; o >>= 1) {
                s  += __shfl_xor_sync(0xffffffff, s,  o);
                s2 += __shfl_xor_sync(0xffffffff, s2, o);
            }
            float mu  = s * (1.f / Hn);
            float var = s2 * (1.f / Hn) - mu * mu;
            float inv = rsqrtf(var + 1e-5f);
#pragma unroll
            for (int j = 0; j < 8; ++j) {
                int c = lane + j * 32;
                float v = (Hs[r * Hn + c] - mu) * inv * g2[c] + be2[c];
                Hs[r * Hn + c] = 0.5f * v * (1.f + erff(v * 0.70710678118654752f));
            }
        }
    }
    __syncthreads();

    float aA[32], aB[32];
#pragma unroll
    for (int r = 0; r < 32; ++r) { aA[r] = 0.f; aB[r] = 0.f; }
    {
        const float4* Hs4 = (const float4*)Hs;
        for (int d = 0; d < Hn; d += 4) {
            float wa0 = W4[(d + 0) * Dn + tid];
            float wa1 = W4[(d + 1) * Dn + tid];
            float wa2 = W4[(d + 2) * Dn + tid];
            float wa3 = W4[(d + 3) * Dn + tid];
            float wb0 = W4[(d + 0) * Dn + tid + 256];
            float wb1 = W4[(d + 1) * Dn + tid + 256];
            float wb2 = W4[(d + 2) * Dn + tid + 256];
            float wb3 = W4[(d + 3) * Dn + tid + 256];
#pragma unroll
            for (int r = 0; r < 32; ++r) {
                float4 h = Hs4[(r * Hn + d) >> 2];
                aA[r] = fmaf(h.x, wa0, aA[r]);
                aA[r] = fmaf(h.y, wa1, aA[r]);
                aA[r] = fmaf(h.z, wa2, aA[r]);
                aA[r] = fmaf(h.w, wa3, aA[r]);
                aB[r] = fmaf(h.x, wb0, aB[r]);
                aB[r] = fmaf(h.y, wb1, aB[r]);
                aB[r] = fmaf(h.z, wb2, aB[r]);
                aB[r] = fmaf(h.w, wb3, aB[r]);
            }
        }
    }

    {
        const int warp = tid >> 5, lane = tid & 31;
        float b4a = b4[tid], b4b = b4[tid + 256];
        for (int r = 0; r < 32; ++r) {
            float f1 = X[(size_t)(row0 + r) * Dn + tid];
            float f2 = X[(size_t)(row0 + r) * Dn + tid + 256];
            float d1 = aA[r] + b4a - f1;
            float d2 = aB[r] + b4b - f2;
            float e = d1 * d1 + d2 * d2;
#pragma unroll
            for (int o = 16; o > 0; o >>= 1) e += __shfl_xor_sync(0xffffffff, e, o);
            if (lane == 0) ep[r * 8 + warp] = e;
        }
        __syncthreads();
        if (tid < 32) {
            float s = 0.f;
#pragma unroll
            for (int w = 0; w < 8; ++w) s += ep[tid * 8 + w];
            g_err[row0 + tid] = s * (1.f / Dn);
        }
    }
}

// ---------------- global mean ----------------
__global__ void reduce_kernel()
{
    __shared__ float s[256];
    int tid = threadIdx.x;
    float a = 0.f;
    for (int i = tid; i < Bn; i += 256) a += g_err[i];
    s[tid] = a;
    __syncthreads();
    for (int o = 128; o > 0; o >>= 1) {
        if (tid < o) s[tid] += s[tid + o];
        __syncthreads();
    }
    if (tid == 0) g_sum = s[0];
}

// ---------------- MDL + output ----------------
__global__ void final_kernel(float* __restrict__ out)
{
    int i = blockIdx.x * 256 + threadIdx.x;
    float scale = g_sum * (1.f / Bn) + 1e-8f;
    float err = g_err[i];
    float eb = (fabsf(err) / scale + logf(2.f * scale)) * 1.4426950408889634f;
    float tb = 14.f + eb;
    out[i]          = err;
    out[Bn + i]     = (Dn * 32.f) / tb;
    out[2 * Bn + i] = tb;
    out[3 * Bn + i] = (float)g_idx[i];
}

// ---------------- launch ----------------
extern "C" void kernel_launch(void* const* d_in, const int* in_sizes, int n_in,
                              void* d_out, int out_size)
{
    const float* X   = (const float*)d_in[0];
    const float* W1  = (const float*)d_in[1];
    const float* b1  = (const float*)d_in[2];
    const float* g1  = (const float*)d_in[3];
    const float* be1 = (const float*)d_in[4];
    const float* W2  = (const float*)d_in[5];
    const float* b2  = (const float*)d_in[6];
    const float* CB  = (const float*)d_in[7];
    const float* W3  = (const float*)d_in[8];
    const float* b3  = (const float*)d_in[9];
    const float* g2  = (const float*)d_in[10];
    const float* be2 = (const float*)d_in[11];
    const float* W4  = (const float*)d_in[12];
    const float* b4  = (const float*)d_in[13];
    float* out = (float*)d_out;

    cudaFuncSetAttribute(encoder_kernel,     cudaFuncAttributeMaxDynamicSharedMemorySize, 98304);
    cudaFuncSetAttribute(dist_coarse_kernel, cudaFuncAttributeMaxDynamicSharedMemorySize, DSM2_TOT);
    cudaFuncSetAttribute(decoder_kernel,     cudaFuncAttributeMaxDynamicSharedMemorySize, 50176);

    c0split_kernel<<<Kn / 8, 256>>>(CB);
    encoder_kernel<<<Bn / 32, 256, 98304>>>(X, W1, b1, g1, be1, W2, b2);
    enorm_kernel<<<Bn / 8, 256>>>();
    dist_coarse_kernel<<<(Bn / 64) * KGROUPS, 256, DSM2_TOT>>>();
    rescore_kernel<<<Bn / 4, 128>>>(CB);
    decoder_kernel<<<Bn / 32, 256, 50176>>>(CB, W3, b3, g2, be2, W4, b4, X);
    reduce_kernel<<<1, 256>>>();
    final_kernel<<<Bn / 256, 256>>>(out);
}

// round 9
// speedup vs baseline: 1.2002x; 1.2002x over previous
#include <cuda_runtime.h>
#include <cuda_bf16.h>
#include <math.h>
#include <stdint.h>

#define Bn 16384
#define Dn 512
#define Kn 16384
#define Hn 256
#define Zn 128
#define LDK2 136                     // padded row stride in bf16 (272B = 17*16 -> conflict-free ldsm)

// ---------------- scratch ----------------
__device__ __align__(16) float g_enc[(size_t)Bn * Zn];              // encoded fp32
__device__ __align__(16) __nv_bfloat16 g_e0p[(size_t)Bn * LDK2];    // bf16(encoded), padded stride
__device__ __align__(16) __nv_bfloat16 g_c0p[(size_t)Kn * LDK2];    // bf16(codebook), padded stride
__device__ float g_negc2[Kn];
__device__ float g_en2[Bn];
__device__ float g_dn2[Bn];
__device__ float g_Rmax2;
__device__ float g_Nmax2;
__device__ float g_smax[Bn];
__device__ float g_cand_val[(size_t)Bn * 48];
__device__ int   g_cand_idx[(size_t)Bn * 48];
__device__ float g_fourth[(size_t)Bn * 16];
__device__ int   g_idx[Bn];
__device__ float g_err[Bn];
__device__ float g_sum;

// ---------------- helpers ----------------
__device__ __forceinline__ uint32_t smem_u32(const void* p) {
    uint32_t a;
    asm("{ .reg .u64 t; cvta.to.shared.u64 t, %1; cvt.u32.u64 %0, t; }" : "=r"(a) : "l"(p));
    return a;
}
__device__ __forceinline__ void ldsm_x4(uint32_t r[4], uint32_t addr) {
    asm volatile("ldmatrix.sync.aligned.m8n8.x4.shared.b16 {%0,%1,%2,%3}, [%4];"
        : "=r"(r[0]), "=r"(r[1]), "=r"(r[2]), "=r"(r[3]) : "r"(addr));
}
__device__ __forceinline__ void mma_bf16(float d[4], const uint32_t a[4], const uint32_t b[2]) {
    asm volatile("mma.sync.aligned.m16n8k16.row.col.f32.bf16.bf16.f32 "
        "{%0,%1,%2,%3}, {%4,%5,%6,%7}, {%8,%9}, {%0,%1,%2,%3};"
        : "+f"(d[0]), "+f"(d[1]), "+f"(d[2]), "+f"(d[3])
        : "r"(a[0]), "r"(a[1]), "r"(a[2]), "r"(a[3]), "r"(b[0]), "r"(b[1]));
}
__device__ __forceinline__ uint32_t pack_bf16(float a, float b) {
    __nv_bfloat162 t = __floats2bfloat162_rn(a, b);
    return *(uint32_t*)&t;
}
// one-shot bulk copy global -> shared with mbarrier complete_tx
__device__ __forceinline__ void bulk_g2s(uint32_t dst, const void* src, uint32_t bytes, uint32_t mbar) {
    asm volatile("cp.async.bulk.shared::cluster.global.mbarrier::complete_tx::bytes [%0], [%1], %2, [%3];"
        :: "r"(dst), "l"(src), "r"(bytes), "r"(mbar) : "memory");
}
#define MBAR_INIT(mb, c) \
    asm volatile("mbarrier.init.shared.b64 [%0], %1;" :: "r"((uint32_t)(mb)), "r"((uint32_t)(c)) : "memory")
#define MBAR_EXPECT_TX(mb, n) \
    asm volatile("mbarrier.arrive.expect_tx.shared.b64 _, [%0], %1;" :: "r"((uint32_t)(mb)), "r"((uint32_t)(n)) : "memory")
#define MBAR_WAIT(mb, par) do { \
    uint32_t _m = (uint32_t)(mb); uint32_t _p = (uint32_t)(par); uint32_t _d; \
    asm volatile("{\n\t.reg .pred p;\n\t" \
        "mbarrier.try_wait.parity.acquire.cta.shared::cta.b64 p, [%1], %2;\n\t" \
        "selp.b32 %0, 1, 0, p;\n\t}" : "=r"(_d) : "r"(_m), "r"(_p) : "memory"); \
    if (!_d) { \
        asm volatile("{\n\t.reg .pred P1;\n\t" \
            "WL_%=:\n\t" \
            "mbarrier.try_wait.parity.acquire.cta.shared::cta.b64 P1, [%0], %1, 0x989680;\n\t" \
            "@P1 bra.uni WD_%=;\n\tbra.uni WL_%=;\n\tWD_%=:\n\t}" \
            :: "r"(_m), "r"(_p) : "memory"); \
    } } while (0)

// ---------------- encoder ----------------
__global__ void encoder_kernel(const float* __restrict__ X,
                               const float* __restrict__ W1, const float* __restrict__ b1,
                               const float* __restrict__ g1, const float* __restrict__ be1,
                               const float* __restrict__ W2, const float* __restrict__ b2)
{
    extern __shared__ float sm[];
    float* Xs = sm;
    float* Hs = sm + 32 * Dn;
    const int tid = threadIdx.x;
    const int row0 = blockIdx.x * 32;

    {
        const float4* Xg = (const float4*)(X + (size_t)row0 * Dn);
        float4* Xs4 = (float4*)Xs;
        for (int i = tid; i < 32 * Dn / 4; i += 256) Xs4[i] = Xg[i];
    }
    __syncthreads();

    const float4* Xs4 = (const float4*)Xs;
    float acc[32];
#pragma unroll
    for (int r = 0; r < 32; ++r) acc[r] = 0.f;
    const int col = tid;
    for (int d = 0; d < Dn; d += 4) {
        float w0 = W1[(d + 0) * Hn + col];
        float w1 = W1[(d + 1) * Hn + col];
        float w2 = W1[(d + 2) * Hn + col];
        float w3 = W1[(d + 3) * Hn + col];
#pragma unroll
        for (int r = 0; r < 32; ++r) {
            float4 x = Xs4[(r * Dn + d) >> 2];
            acc[r] = fmaf(x.x, w0, acc[r]);
            acc[r] = fmaf(x.y, w1, acc[r]);
            acc[r] = fmaf(x.z, w2, acc[r]);
            acc[r] = fmaf(x.w, w3, acc[r]);
        }
    }
    {
        float bb = b1[col];
#pragma unroll
        for (int r = 0; r < 32; ++r) Hs[r * Hn + col] = acc[r] + bb;
    }
    __syncthreads();

    {
        const int warp = tid >> 5, lane = tid & 31;
        for (int rr = 0; rr < 4; ++rr) {
            int r = warp + rr * 8;
            float s = 0.f, s2 = 0.f;
#pragma unroll
            for (int j = 0; j < 8; ++j) {
                float v = Hs[r * Hn + lane + j * 32];
                s += v; s2 += v * v;
            }
#pragma unroll
            for (int o = 16; o > 0; o >>= 1) {
                s  += __shfl_xor_sync(0xffffffff, s,  o);
                s2 += __shfl_xor_sync(0xffffffff, s2, o);
            }
            float mu  = s * (1.f / Hn);
            float var = s2 * (1.f / Hn) - mu * mu;
            float inv = rsqrtf(var + 1e-5f);
#pragma unroll
            for (int j = 0; j < 8; ++j) {
                int c = lane + j * 32;
                float v = (Hs[r * Hn + c] - mu) * inv * g1[c] + be1[c];
                Hs[r * Hn + c] = 0.5f * v * (1.f + erff(v * 0.70710678118654752f));
            }
        }
    }
    __syncthreads();

    {
        const float4* Hs4 = (const float4*)Hs;
        const int c2 = tid & 127;
        const int rbase = (tid >> 7) * 16;
        float a2[16];
#pragma unroll
        for (int r = 0; r < 16; ++r) a2[r] = 0.f;
        for (int d = 0; d < Hn; d += 4) {
            float w0 = W2[(d + 0) * Zn + c2];
            float w1 = W2[(d + 1) * Zn + c2];
            float w2 = W2[(d + 2) * Zn + c2];
            float w3 = W2[(d + 3) * Zn + c2];
#pragma unroll
            for (int r = 0; r < 16; ++r) {
                float4 h = Hs4[((rbase + r) * Hn + d) >> 2];
                a2[r] = fmaf(h.x, w0, a2[r]);
                a2[r] = fmaf(h.y, w1, a2[r]);
                a2[r] = fmaf(h.z, w2, a2[r]);
                a2[r] = fmaf(h.w, w3, a2[r]);
            }
        }
        float bb = b2[c2];
#pragma unroll
        for (int r = 0; r < 16; ++r)
            g_enc[(size_t)(row0 + rbase + r) * Zn + c2] = a2[r] + bb;
    }
}

// ---------------- per-row e0 (padded) + norms ----------------
__global__ void enorm_kernel()
{
    int gw = (blockIdx.x * 256 + threadIdx.x) >> 5;
    int lane = threadIdx.x & 31;
    const float4 e4 = ((const float4*)(g_enc + (size_t)gw * 128))[lane];
    float e0x = __bfloat162float(__float2bfloat16(e4.x));
    float e0y = __bfloat162float(__float2bfloat16(e4.y));
    float e0z = __bfloat162float(__float2bfloat16(e4.z));
    float e0w = __bfloat162float(__float2bfloat16(e4.w));
    *(uint2*)(g_e0p + (size_t)gw * LDK2 + lane * 4) =
        make_uint2(pack_bf16(e4.x, e4.y), pack_bf16(e4.z, e4.w));
    float en2 = e4.x*e4.x + e4.y*e4.y + e4.z*e4.z + e4.w*e4.w;
    float dx = e4.x - e0x, dy = e4.y - e0y, dz = e4.z - e0z, dw = e4.w - e0w;
    float dn2 = dx*dx + dy*dy + dz*dz + dw*dw;
#pragma unroll
    for (int o = 16; o > 0; o >>= 1) {
        en2 += __shfl_xor_sync(0xffffffff, en2, o);
        dn2 += __shfl_xor_sync(0xffffffff, dn2, o);
    }
    if (lane == 0) { g_en2[gw] = en2; g_dn2[gw] = dn2; }
}

// ---------------- codebook prep (padded) ----------------
__global__ void c0split_kernel(const float* __restrict__ C)
{
    int code = (blockIdx.x * 256 + threadIdx.x) >> 5;
    int lane = threadIdx.x & 31;
    const float4 c4 = ((const float4*)(C + (size_t)code * 128))[lane];
    float c0x = __bfloat162float(__float2bfloat16(c4.x));
    float c0y = __bfloat162float(__float2bfloat16(c4.y));
    float c0z = __bfloat162float(__float2bfloat16(c4.z));
    float c0w = __bfloat162float(__float2bfloat16(c4.w));
    *(uint2*)(g_c0p + (size_t)code * LDK2 + lane * 4) =
        make_uint2(pack_bf16(c4.x, c4.y), pack_bf16(c4.z, c4.w));
    float c2 = c4.x*c4.x + c4.y*c4.y + c4.z*c4.z + c4.w*c4.w;
    float n2 = c0x*c0x + c0y*c0y + c0z*c0z + c0w*c0w;
    float dx = c4.x - c0x, dy = c4.y - c0y, dz = c4.z - c0z, dw = c4.w - c0w;
    float r2 = dx*dx + dy*dy + dz*dz + dw*dw;
#pragma unroll
    for (int o = 16; o > 0; o >>= 1) {
        c2 += __shfl_xor_sync(0xffffffff, c2, o);
        n2 += __shfl_xor_sync(0xffffffff, n2, o);
        r2 += __shfl_xor_sync(0xffffffff, r2, o);
    }
    if (lane == 0) {
        g_negc2[code] = -0.5f * c2;
        atomicMax((int*)&g_Rmax2, __float_as_int(r2));
        atomicMax((int*)&g_Nmax2, __float_as_int(n2));
    }
}

// ---------------- coarse distance: R7 structure, bulk-copy loads ----------------
#define A_BYTES (64 * LDK2 * 2)          // 17408
#define TILE_BYTES (128 * LDK2 * 2)      // 34816
#define SB_A 0
#define SB_B0 A_BYTES
#define SB_MBAR (A_BYTES + 2 * TILE_BYTES)   // 87040
#define SB_RED (SB_MBAR + 64)
#define DSM2_TOT (SB_RED + 64 * 16 * 4)

__global__ __launch_bounds__(256, 2) void dist_coarse_kernel()
{
    extern __shared__ char smem[];
    float* redsm = (float*)(smem + SB_RED);

    const int tid  = threadIdx.x;
    const int lane = tid & 31;
    const int wid  = tid >> 5;
    const int warp_m = wid >> 2;
    const int warp_n = wid & 3;
    const int row0 = blockIdx.x * 64;

    const uint32_t sbA   = smem_u32(smem) + SB_A;
    const uint32_t sbB0  = smem_u32(smem) + SB_B0;
    const uint32_t mbA   = smem_u32(smem) + SB_MBAR;
    const uint32_t mbB0  = mbA + 8;
    const uint32_t mbB1  = mbA + 16;

    if (tid == 0) {
        MBAR_INIT(mbA, 1);
        MBAR_INIT(mbB0, 1);
        MBAR_INIT(mbB1, 1);
    }
    __syncthreads();

    if (tid == 0) {
        MBAR_EXPECT_TX(mbA, A_BYTES);
        bulk_g2s(sbA, g_e0p + (size_t)row0 * LDK2, A_BYTES, mbA);
        MBAR_EXPECT_TX(mbB0, TILE_BYTES);
        bulk_g2s(sbB0, g_c0p, TILE_BYTES, mbB0);
    }

    uint32_t a_addr[2];
#pragma unroll
    for (int mi = 0; mi < 2; ++mi)
        a_addr[mi] = sbA + ((warp_m * 32 + mi * 16 + (lane & 15)) * LDK2 + (lane >> 4) * 8) * 2;
    uint32_t b_addr[2];
#pragma unroll
    for (int njp = 0; njp < 2; ++njp)
        b_addr[njp] = sbB0 + ((warp_n * 32 + njp * 16 + (lane & 7) + ((lane >> 4) << 3)) * LDK2
                              + ((lane >> 3) & 1) * 8) * 2;

    float v1[4], v2[4], v3[4], v4[4];
    int   i1[4], i2[4], i3[4];
#pragma unroll
    for (int r = 0; r < 4; ++r) {
        v1[r] = v2[r] = v3[r] = v4[r] = -INFINITY;
        i1[r] = i2[r] = i3[r] = 0;
    }

    const int cq = (lane & 3) * 2;

    MBAR_WAIT(mbA, 0);

    for (int t = 0, kt = 0; t < 128; ++t, kt += 128) {
        const uint32_t bufo = (uint32_t)(t & 1) * TILE_BYTES;
        // issue next tile into the other buffer (read last at t-1; end-of-(t-1) sync done)
        if (tid == 0 && t < 127) {
            uint32_t mb = ((t + 1) & 1) ? mbB1 : mbB0;
            MBAR_EXPECT_TX(mb, TILE_BYTES);
            bulk_g2s(sbB0 + ((t + 1) & 1) * TILE_BYTES,
                     g_c0p + (size_t)(kt + 128) * LDK2, TILE_BYTES, mb);
        }
        // wait current tile: buffer t&1, k-th use parity = (t>>1)&1
        MBAR_WAIT((t & 1) ? mbB1 : mbB0, (t >> 1) & 1);

        // -0.5||c||^2 loads issued early, consumed in epilogue (latency hidden by MMA loop)
        float nc[8];
#pragma unroll
        for (int nj = 0; nj < 4; ++nj) {
            nc[nj * 2]     = g_negc2[kt + warp_n * 32 + nj * 8 + cq];
            nc[nj * 2 + 1] = g_negc2[kt + warp_n * 32 + nj * 8 + cq + 1];
        }

        float acc[2][4][4];
#pragma unroll
        for (int mi = 0; mi < 2; ++mi)
#pragma unroll
            for (int nj = 0; nj < 4; ++nj)
#pragma unroll
                for (int k = 0; k < 4; ++k) acc[mi][nj][k] = 0.f;

#pragma unroll
        for (int s = 0; s < 8; ++s) {
            uint32_t af[2][4], bf[2][4];
#pragma unroll
            for (int mi = 0; mi < 2; ++mi) ldsm_x4(af[mi], a_addr[mi] + s * 32);
#pragma unroll
            for (int njp = 0; njp < 2; ++njp) ldsm_x4(bf[njp], b_addr[njp] + bufo + s * 32);
#pragma unroll
            for (int mi = 0; mi < 2; ++mi)
#pragma unroll
                for (int nj = 0; nj < 4; ++nj)
                    mma_bf16(acc[mi][nj], af[mi], bf[nj >> 1] + (nj & 1) * 2);
        }

        // epilogue: add -0.5||c||^2, max-of-8 quick reject, rare insert
#pragma unroll
        for (int mi = 0; mi < 2; ++mi) {
#pragma unroll
            for (int h = 0; h < 2; ++h) {
                const int ri = mi * 2 + h;
                float s0 = acc[mi][0][h * 2]     + nc[0];
                float s1 = acc[mi][0][h * 2 + 1] + nc[1];
                float s2 = acc[mi][1][h * 2]     + nc[2];
                float s3 = acc[mi][1][h * 2 + 1] + nc[3];
                float s4 = acc[mi][2][h * 2]     + nc[4];
                float s5 = acc[mi][2][h * 2 + 1] + nc[5];
                float s6 = acc[mi][3][h * 2]     + nc[6];
                float s7 = acc[mi][3][h * 2 + 1] + nc[7];
                float m8 = fmaxf(fmaxf(fmaxf(s0, s1), fmaxf(s2, s3)),
                                 fmaxf(fmaxf(s4, s5), fmaxf(s6, s7)));
                if (m8 > v4[ri]) {
                    float sv[8] = {s0, s1, s2, s3, s4, s5, s6, s7};
#pragma unroll
                    for (int j = 0; j < 8; ++j) {
                        float v = sv[j];
                        if (v > v4[ri]) {
                            int idx = kt + warp_n * 32 + (j >> 1) * 8 + cq + (j & 1);
                            if (v > v1[ri]) {
                                v4[ri] = v3[ri]; v3[ri] = v2[ri]; i3[ri] = i2[ri];
                                v2[ri] = v1[ri]; i2[ri] = i1[ri];
                                v1[ri] = v; i1[ri] = idx;
                            } else if (v > v2[ri]) {
                                v4[ri] = v3[ri]; v3[ri] = v2[ri]; i3[ri] = i2[ri];
                                v2[ri] = v; i2[ri] = idx;
                            } else if (v > v3[ri]) {
                                v4[ri] = v3[ri]; v3[ri] = v; i3[ri] = idx;
                            } else {
                                v4[ri] = v;
                            }
                        }
                    }
                }
            }
        }
        __syncthreads();   // all reads of buf (t&1) done before it is re-filled at t+1
    }

    // write candidates + v4; reduce smax
    const int slot = warp_n * 4 + (lane & 3);
#pragma unroll
    for (int ri = 0; ri < 4; ++ri) {
        int mi = ri >> 1, h = ri & 1;
        int lrow = warp_m * 32 + mi * 16 + (lane >> 2) + h * 8;
        size_t row = (size_t)(row0 + lrow);
        g_cand_val[row * 48 + slot * 3]     = v1[ri];
        g_cand_idx[row * 48 + slot * 3]     = i1[ri];
        g_cand_val[row * 48 + slot * 3 + 1] = v2[ri];
        g_cand_idx[row * 48 + slot * 3 + 1] = i2[ri];
        g_cand_val[row * 48 + slot * 3 + 2] = v3[ri];
        g_cand_idx[row * 48 + slot * 3 + 2] = i3[ri];
        g_fourth[row * 16 + slot] = v4[ri];
        redsm[lrow * 16 + slot] = v1[ri];
    }
    __syncthreads();
    if (tid < 64) {
        float m = redsm[tid * 16];
#pragma unroll
        for (int w = 1; w < 16; ++w) m = fmaxf(m, redsm[tid * 16 + w]);
        g_smax[row0 + tid] = m;
    }
}

// ---------------- exact rescore (warp per row) ----------------
__global__ void rescore_kernel(const float* __restrict__ CB)
{
    const int r = blockIdx.x * 4 + (threadIdx.x >> 5);
    const int lane = threadIdx.x & 31;

    float delta = sqrtf(g_en2[r]) * sqrtf(g_Rmax2) + sqrtf(g_dn2[r]) * sqrtf(g_Nmax2);
    float thresh = g_smax[r] - 1.05f * delta - 1e-4f;

    float th = (lane < 16) ? g_fourth[(size_t)r * 16 + lane] : -INFINITY;
    bool flag = __ballot_sync(0xffffffff, th >= thresh) != 0;

    const float4 e4 = ((const float4*)(g_enc + (size_t)r * 128))[lane];

    float bs = -INFINITY;
    int bi = 0x7fffffff;

    if (!flag) {
        for (int s = 0; s < 48; ++s) {
            float v = g_cand_val[(size_t)r * 48 + s];
            if (v >= thresh) {
                int idx = g_cand_idx[(size_t)r * 48 + s];
                float4 c4 = ((const float4*)(CB + (size_t)idx * 128))[lane];
                float d = e4.x*c4.x + e4.y*c4.y + e4.z*c4.z + e4.w*c4.w;
#pragma unroll
                for (int o = 16; o > 0; o >>= 1) d += __shfl_xor_sync(0xffffffff, d, o);
                float sx = d + g_negc2[idx];
                if (sx > bs || (sx == bs && idx < bi)) { bs = sx; bi = idx; }
            }
        }
    } else {
        for (int k = 0; k < Kn; ++k) {
            float4 c4 = ((const float4*)(CB + (size_t)k * 128))[lane];
            float d = e4.x*c4.x + e4.y*c4.y + e4.z*c4.z + e4.w*c4.w;
#pragma unroll
            for (int o = 16; o > 0; o >>= 1) d += __shfl_xor_sync(0xffffffff, d, o);
            float sx = d + g_negc2[k];
            if (sx > bs) { bs = sx; bi = k; }
        }
    }
    if (lane == 0) g_idx[r] = bi;
}

// ---------------- decoder ----------------
__global__ void decoder_kernel(const float* __restrict__ C,
                               const float* __restrict__ W3, const float* __restrict__ b3,
                               const float* __restrict__ g2, const float* __restrict__ be2,
                               const float* __restrict__ W4, const float* __restrict__ b4,
                               const float* __restrict__ X)
{
    extern __shared__ float sm[];
    float* Qs = sm;
    float* Hs = sm + 32 * Zn;
    float* ep = Hs + 32 * Hn;
    const int tid = threadIdx.x;
    const int row0 = blockIdx.x * 32;

    for (int i = tid; i < 32 * 32; i += 256) {
        int r = i >> 5, d4 = i & 31;
        int code = g_idx[row0 + r];
        ((float4*)Qs)[r * 32 + d4] = ((const float4*)C)[(size_t)code * 32 + d4];
    }
    __syncthreads();

    {
        const float4* Qs4 = (const float4*)Qs;
        float acc[32];
#pragma unroll
        for (int r = 0; r < 32; ++r) acc[r] = 0.f;
        const int col = tid;
        for (int d = 0; d < Zn; d += 4) {
            float w0 = W3[(d + 0) * Hn + col];
            float w1 = W3[(d + 1) * Hn + col];
            float w2 = W3[(d + 2) * Hn + col];
            float w3 = W3[(d + 3) * Hn + col];
#pragma unroll
            for (int r = 0; r < 32; ++r) {
                float4 q = Qs4[(r * Zn + d) >> 2];
                acc[r] = fmaf(q.x, w0, acc[r]);
                acc[r] = fmaf(q.y, w1, acc[r]);
                acc[r] = fmaf(q.z, w2, acc[r]);
                acc[r] = fmaf(q.w, w3, acc[r]);
            }
        }
        float bb = b3[col];
#pragma unroll
        for (int r = 0; r < 32; ++r) Hs[r * Hn + col] = acc[r] + bb;
    }
    __syncthreads();

    {
        const int warp = tid >> 5, lane = tid & 31;
        for (int rr = 0; rr < 4; ++rr) {
            int r = warp + rr * 8;
            float s = 0.f, s2 = 0.f;
#pragma unroll
            for (int j = 0; j < 8; ++j) {
                float v = Hs[r * Hn + lane + j * 32];
                s += v; s2 += v * v;
            }
#pragma unroll
            for (int o = 16; o > 0; o >>= 1) {
                s  += __shfl_xor_sync(0xffffffff, s,  o);
                s2 += __shfl_xor_sync(0xffffffff, s2, o);
            }
            float mu  = s * (1.f / Hn);
            float var = s2 * (1.f / Hn) - mu * mu;
            float inv = rsqrtf(var + 1e-5f);
#pragma unroll
            for (int j = 0; j < 8; ++j) {
                int c = lane + j * 32;
                float v = (Hs[r * Hn + c] - mu) * inv * g2[c] + be2[c];
                Hs[r * Hn + c] = 0.5f * v * (1.f + erff(v * 0.70710678118654752f));
            }
        }
    }
    __syncthreads();

    float aA[32], aB[32];
#pragma unroll
    for (int r = 0; r < 32; ++r) { aA[r] = 0.f; aB[r] = 0.f; }
    {
        const float4* Hs4 = (const float4*)Hs;
        for (int d = 0; d < Hn; d += 4) {
            float wa0 = W4[(d + 0) * Dn + tid];
            float wa1 = W4[(d + 1) * Dn + tid];
            float wa2 = W4[(d + 2) * Dn + tid];
            float wa3 = W4[(d + 3) * Dn + tid];
            float wb0 = W4[(d + 0) * Dn + tid + 256];
            float wb1 = W4[(d + 1) * Dn + tid + 256];
            float wb2 = W4[(d + 2) * Dn + tid + 256];
            float wb3 = W4[(d + 3) * Dn + tid + 256];
#pragma unroll
            for (int r = 0; r < 32; ++r) {
                float4 h = Hs4[(r * Hn + d) >> 2];
                aA[r] = fmaf(h.x, wa0, aA[r]);
                aA[r] = fmaf(h.y, wa1, aA[r]);
                aA[r] = fmaf(h.z, wa2, aA[r]);
                aA[r] = fmaf(h.w, wa3, aA[r]);
                aB[r] = fmaf(h.x, wb0, aB[r]);
                aB[r] = fmaf(h.y, wb1, aB[r]);
                aB[r] = fmaf(h.z, wb2, aB[r]);
                aB[r] = fmaf(h.w, wb3, aB[r]);
            }
        }
    }

    {
        const int warp = tid >> 5, lane = tid & 31;
        float b4a = b4[tid], b4b = b4[tid + 256];
        for (int r = 0; r < 32; ++r) {
            float f1 = X[(size_t)(row0 + r) * Dn + tid];
            float f2 = X[(size_t)(row0 + r) * Dn + tid + 256];
            float d1 = aA[r] + b4a - f1;
            float d2 = aB[r] + b4b - f2;
            float e = d1 * d1 + d2 * d2;
#pragma unroll
            for (int o = 16; o > 0; o >>= 1) e += __shfl_xor_sync(0xffffffff, e, o);
            if (lane == 0) ep[r * 8 + warp] = e;
        }
        __syncthreads();
        if (tid < 32) {
            float s = 0.f;
#pragma unroll
            for (int w = 0; w < 8; ++w) s += ep[tid * 8 + w];
            g_err[row0 + tid] = s * (1.f / Dn);
        }
    }
}

// ---------------- global mean ----------------
__global__ void reduce_kernel()
{
    __shared__ float s[256];
    int tid = threadIdx.x;
    float a = 0.f;
    for (int i = tid; i < Bn; i += 256) a += g_err[i];
    s[tid] = a;
    __syncthreads();
    for (int o = 128; o > 0; o >>= 1) {
        if (tid < o) s[tid] += s[tid + o];
        __syncthreads();
    }
    if (tid == 0) g_sum = s[0];
}

// ---------------- MDL + output ----------------
__global__ void final_kernel(float* __restrict__ out)
{
    int i = blockIdx.x * 256 + threadIdx.x;
    float scale = g_sum * (1.f / Bn) + 1e-8f;
    float err = g_err[i];
    float eb = (fabsf(err) / scale + logf(2.f * scale)) * 1.4426950408889634f;
    float tb = 14.f + eb;
    out[i]          = err;
    out[Bn + i]     = (Dn * 32.f) / tb;
    out[2 * Bn + i] = tb;
    out[3 * Bn + i] = (float)g_idx[i];
}

// ---------------- launch ----------------
extern "C" void kernel_launch(void* const* d_in, const int* in_sizes, int n_in,
                              void* d_out, int out_size)
{
    const float* X   = (const float*)d_in[0];
    const float* W1  = (const float*)d_in[1];
    const float* b1  = (const float*)d_in[2];
    const float* g1  = (const float*)d_in[3];
    const float* be1 = (const float*)d_in[4];
    const float* W2  = (const float*)d_in[5];
    const float* b2  = (const float*)d_in[6];
    const float* CB  = (const float*)d_in[7];
    const float* W3  = (const float*)d_in[8];
    const float* b3  = (const float*)d_in[9];
    const float* g2  = (const float*)d_in[10];
    const float* be2 = (const float*)d_in[11];
    const float* W4  = (const float*)d_in[12];
    const float* b4  = (const float*)d_in[13];
    float* out = (float*)d_out;

    cudaFuncSetAttribute(encoder_kernel,     cudaFuncAttributeMaxDynamicSharedMemorySize, 98304);
    cudaFuncSetAttribute(dist_coarse_kernel, cudaFuncAttributeMaxDynamicSharedMemorySize, DSM2_TOT);
    cudaFuncSetAttribute(decoder_kernel,     cudaFuncAttributeMaxDynamicSharedMemorySize, 50176);

    c0split_kernel<<<Kn / 8, 256>>>(CB);
    encoder_kernel<<<Bn / 32, 256, 98304>>>(X, W1, b1, g1, be1, W2, b2);
    enorm_kernel<<<Bn / 8, 256>>>();
    dist_coarse_kernel<<<Bn / 64, 256, DSM2_TOT>>>();
    rescore_kernel<<<Bn / 4, 128>>>(CB);
    decoder_kernel<<<Bn / 32, 256, 50176>>>(CB, W3, b3, g2, be2, W4, b4, X);
    reduce_kernel<<<1, 256>>>();
    final_kernel<<<Bn / 256, 256>>>(out);
}

// round 10
// speedup vs baseline: 1.2665x; 1.0553x over previous
#include <cuda_runtime.h>
#include <cuda_bf16.h>
#include <math.h>
#include <stdint.h>

#define Bn 16384
#define Dn 512
#define Kn 16384
#define Hn 256
#define Zn 128
#define LDK2 136                     // padded row stride in bf16 (272B); bytes 256..259 carry -0.5||c||^2

// ---------------- scratch ----------------
__device__ __align__(16) float g_enc[(size_t)Bn * Zn];
__device__ __align__(16) __nv_bfloat16 g_e0p[(size_t)Bn * LDK2];
__device__ __align__(16) __nv_bfloat16 g_c0p[(size_t)Kn * LDK2];
__device__ float g_negc2[Kn];
__device__ float g_en2[Bn];
__device__ float g_dn2[Bn];
__device__ float g_Rmax2;
__device__ float g_Nmax2;
__device__ float g_smax[Bn];
__device__ float g_cand_val[(size_t)Bn * 48];
__device__ int   g_cand_idx[(size_t)Bn * 48];
__device__ float g_fourth[(size_t)Bn * 16];
__device__ int   g_idx[Bn];
__device__ float g_err[Bn];
__device__ float g_sum;

// ---------------- helpers ----------------
__device__ __forceinline__ uint32_t smem_u32(const void* p) {
    uint32_t a;
    asm("{ .reg .u64 t; cvta.to.shared.u64 t, %1; cvt.u32.u64 %0, t; }" : "=r"(a) : "l"(p));
    return a;
}
__device__ __forceinline__ void ldsm_x4(uint32_t r[4], uint32_t addr) {
    asm volatile("ldmatrix.sync.aligned.m8n8.x4.shared.b16 {%0,%1,%2,%3}, [%4];"
        : "=r"(r[0]), "=r"(r[1]), "=r"(r[2]), "=r"(r[3]) : "r"(addr));
}
__device__ __forceinline__ void mma_bf16(float d[4], const uint32_t a[4], const uint32_t b[2]) {
    asm volatile("mma.sync.aligned.m16n8k16.row.col.f32.bf16.bf16.f32 "
        "{%0,%1,%2,%3}, {%4,%5,%6,%7}, {%8,%9}, {%0,%1,%2,%3};"
        : "+f"(d[0]), "+f"(d[1]), "+f"(d[2]), "+f"(d[3])
        : "r"(a[0]), "r"(a[1]), "r"(a[2]), "r"(a[3]), "r"(b[0]), "r"(b[1]));
}
__device__ __forceinline__ uint32_t pack_bf16(float a, float b) {
    __nv_bfloat162 t = __floats2bfloat162_rn(a, b);
    return *(uint32_t*)&t;
}
__device__ __forceinline__ void bulk_g2s(uint32_t dst, const void* src, uint32_t bytes, uint32_t mbar) {
    asm volatile("cp.async.bulk.shared::cluster.global.mbarrier::complete_tx::bytes [%0], [%1], %2, [%3];"
        :: "r"(dst), "l"(src), "r"(bytes), "r"(mbar) : "memory");
}
#define MBAR_INIT(mb, c) \
    asm volatile("mbarrier.init.shared.b64 [%0], %1;" :: "r"((uint32_t)(mb)), "r"((uint32_t)(c)) : "memory")
#define MBAR_EXPECT_TX(mb, n) \
    asm volatile("mbarrier.arrive.expect_tx.shared.b64 _, [%0], %1;" :: "r"((uint32_t)(mb)), "r"((uint32_t)(n)) : "memory")
#define MBAR_ARRIVE(mb) \
    asm volatile("mbarrier.arrive.shared.b64 _, [%0];" :: "r"((uint32_t)(mb)) : "memory")
#define MBAR_WAIT(mb, par) do { \
    uint32_t _m = (uint32_t)(mb); uint32_t _p = (uint32_t)(par); uint32_t _d; \
    asm volatile("{\n\t.reg .pred p;\n\t" \
        "mbarrier.try_wait.parity.acquire.cta.shared::cta.b64 p, [%1], %2;\n\t" \
        "selp.b32 %0, 1, 0, p;\n\t}" : "=r"(_d) : "r"(_m), "r"(_p) : "memory"); \
    if (!_d) { \
        asm volatile("{\n\t.reg .pred P1;\n\t" \
            "WL_%=:\n\t" \
            "mbarrier.try_wait.parity.acquire.cta.shared::cta.b64 P1, [%0], %1, 0x989680;\n\t" \
            "@P1 bra.uni WD_%=;\n\tbra.uni WL_%=;\n\tWD_%=:\n\t}" \
            :: "r"(_m), "r"(_p) : "memory"); \
    } } while (0)

// ---------------- encoder ----------------
__global__ void encoder_kernel(const float* __restrict__ X,
                               const float* __restrict__ W1, const float* __restrict__ b1,
                               const float* __restrict__ g1, const float* __restrict__ be1,
                               const float* __restrict__ W2, const float* __restrict__ b2)
{
    extern __shared__ float sm[];
    float* Xs = sm;
    float* Hs = sm + 32 * Dn;
    const int tid = threadIdx.x;
    const int row0 = blockIdx.x * 32;

    {
        const float4* Xg = (const float4*)(X + (size_t)row0 * Dn);
        float4* Xs4 = (float4*)Xs;
        for (int i = tid; i < 32 * Dn / 4; i += 256) Xs4[i] = Xg[i];
    }
    __syncthreads();

    const float4* Xs4 = (const float4*)Xs;
    float acc[32];
#pragma unroll
    for (int r = 0; r < 32; ++r) acc[r] = 0.f;
    const int col = tid;
    for (int d = 0; d < Dn; d += 4) {
        float w0 = W1[(d + 0) * Hn + col];
        float w1 = W1[(d + 1) * Hn + col];
        float w2 = W1[(d + 2) * Hn + col];
        float w3 = W1[(d + 3) * Hn + col];
#pragma unroll
        for (int r = 0; r < 32; ++r) {
            float4 x = Xs4[(r * Dn + d) >> 2];
            acc[r] = fmaf(x.x, w0, acc[r]);
            acc[r] = fmaf(x.y, w1, acc[r]);
            acc[r] = fmaf(x.z, w2, acc[r]);
            acc[r] = fmaf(x.w, w3, acc[r]);
        }
    }
    {
        float bb = b1[col];
#pragma unroll
        for (int r = 0; r < 32; ++r) Hs[r * Hn + col] = acc[r] + bb;
    }
    __syncthreads();

    {
        const int warp = tid >> 5, lane = tid & 31;
        for (int rr = 0; rr < 4; ++rr) {
            int r = warp + rr * 8;
            float s = 0.f, s2 = 0.f;
#pragma unroll
            for (int j = 0; j < 8; ++j) {
                float v = Hs[r * Hn + lane + j * 32];
                s += v; s2 += v * v;
            }
#pragma unroll
            for (int o = 16; o > 0; o >>= 1) {
                s  += __shfl_xor_sync(0xffffffff, s,  o);
                s2 += __shfl_xor_sync(0xffffffff, s2, o);
            }
            float mu  = s * (1.f / Hn);
            float var = s2 * (1.f / Hn) - mu * mu;
            float inv = rsqrtf(var + 1e-5f);
#pragma unroll
            for (int j = 0; j < 8; ++j) {
                int c = lane + j * 32;
                float v = (Hs[r * Hn + c] - mu) * inv * g1[c] + be1[c];
                Hs[r * Hn + c] = 0.5f * v * (1.f + erff(v * 0.70710678118654752f));
            }
        }
    }
    __syncthreads();

    {
        const float4* Hs4 = (const float4*)Hs;
        const int c2 = tid & 127;
        const int rbase = (tid >> 7) * 16;
        float a2[16];
#pragma unroll
        for (int r = 0; r < 16; ++r) a2[r] = 0.f;
        for (int d = 0; d < Hn; d += 4) {
            float w0 = W2[(d + 0) * Zn + c2];
            float w1 = W2[(d + 1) * Zn + c2];
            float w2 = W2[(d + 2) * Zn + c2];
            float w3 = W2[(d + 3) * Zn + c2];
#pragma unroll
            for (int r = 0; r < 16; ++r) {
                float4 h = Hs4[((rbase + r) * Hn + d) >> 2];
                a2[r] = fmaf(h.x, w0, a2[r]);
                a2[r] = fmaf(h.y, w1, a2[r]);
                a2[r] = fmaf(h.z, w2, a2[r]);
                a2[r] = fmaf(h.w, w3, a2[r]);
            }
        }
        float bb = b2[c2];
#pragma unroll
        for (int r = 0; r < 16; ++r)
            g_enc[(size_t)(row0 + rbase + r) * Zn + c2] = a2[r] + bb;
    }
}

// ---------------- per-row e0 (padded) + norms ----------------
__global__ void enorm_kernel()
{
    int gw = (blockIdx.x * 256 + threadIdx.x) >> 5;
    int lane = threadIdx.x & 31;
    const float4 e4 = ((const float4*)(g_enc + (size_t)gw * 128))[lane];
    float e0x = __bfloat162float(__float2bfloat16(e4.x));
    float e0y = __bfloat162float(__float2bfloat16(e4.y));
    float e0z = __bfloat162float(__float2bfloat16(e4.z));
    float e0w = __bfloat162float(__float2bfloat16(e4.w));
    *(uint2*)(g_e0p + (size_t)gw * LDK2 + lane * 4) =
        make_uint2(pack_bf16(e4.x, e4.y), pack_bf16(e4.z, e4.w));
    float en2 = e4.x*e4.x + e4.y*e4.y + e4.z*e4.z + e4.w*e4.w;
    float dx = e4.x - e0x, dy = e4.y - e0y, dz = e4.z - e0z, dw = e4.w - e0w;
    float dn2 = dx*dx + dy*dy + dz*dz + dw*dw;
#pragma unroll
    for (int o = 16; o > 0; o >>= 1) {
        en2 += __shfl_xor_sync(0xffffffff, en2, o);
        dn2 += __shfl_xor_sync(0xffffffff, dn2, o);
    }
    if (lane == 0) { g_en2[gw] = en2; g_dn2[gw] = dn2; }
}

// ---------------- codebook prep (padded; nc stashed in row padding) ----------------
__global__ void c0split_kernel(const float* __restrict__ C)
{
    int code = (blockIdx.x * 256 + threadIdx.x) >> 5;
    int lane = threadIdx.x & 31;
    const float4 c4 = ((const float4*)(C + (size_t)code * 128))[lane];
    float c0x = __bfloat162float(__float2bfloat16(c4.x));
    float c0y = __bfloat162float(__float2bfloat16(c4.y));
    float c0z = __bfloat162float(__float2bfloat16(c4.z));
    float c0w = __bfloat162float(__float2bfloat16(c4.w));
    *(uint2*)(g_c0p + (size_t)code * LDK2 + lane * 4) =
        make_uint2(pack_bf16(c4.x, c4.y), pack_bf16(c4.z, c4.w));
    float c2 = c4.x*c4.x + c4.y*c4.y + c4.z*c4.z + c4.w*c4.w;
    float n2 = c0x*c0x + c0y*c0y + c0z*c0z + c0w*c0w;
    float dx = c4.x - c0x, dy = c4.y - c0y, dz = c4.z - c0z, dw = c4.w - c0w;
    float r2 = dx*dx + dy*dy + dz*dz + dw*dw;
#pragma unroll
    for (int o = 16; o > 0; o >>= 1) {
        c2 += __shfl_xor_sync(0xffffffff, c2, o);
        n2 += __shfl_xor_sync(0xffffffff, n2, o);
        r2 += __shfl_xor_sync(0xffffffff, r2, o);
    }
    if (lane == 0) {
        float nc = -0.5f * c2;
        g_negc2[code] = nc;
        // stash nc in the 16-byte row padding (bytes 256..259 of the 272B row)
        *(float*)((char*)g_c0p + (size_t)code * (LDK2 * 2) + 256) = nc;
        atomicMax((int*)&g_Rmax2, __float_as_int(r2));
        atomicMax((int*)&g_Nmax2, __float_as_int(n2));
    }
}

// ---------------- coarse distance: mbarrier ring, no per-tile CTA barrier ----------------
#define A_BYTES (64 * LDK2 * 2)          // 17408
#define TILE_BYTES (128 * LDK2 * 2)      // 34816
#define SB_A 0
#define SB_B0 A_BYTES
#define SB_MBAR (A_BYTES + 2 * TILE_BYTES)   // 87040: [mbA, full0, full1, empty0, empty1]
#define SB_RED (SB_MBAR + 64)
#define DSM2_TOT (SB_RED + 64 * 16 * 4)

__global__ __launch_bounds__(256, 2) void dist_coarse_kernel()
{
    extern __shared__ char smem[];
    float* redsm = (float*)(smem + SB_RED);

    const int tid  = threadIdx.x;
    const int lane = tid & 31;
    const int wid  = tid >> 5;
    const int warp_m = wid >> 2;
    const int warp_n = wid & 3;
    const int row0 = blockIdx.x * 64;

    const uint32_t sbA    = smem_u32(smem) + SB_A;
    const uint32_t sbB0   = smem_u32(smem) + SB_B0;
    const uint32_t mbA    = smem_u32(smem) + SB_MBAR;
    const uint32_t mbF0   = mbA + 8;
    const uint32_t mbF1   = mbA + 16;
    const uint32_t mbE0   = mbA + 24;
    const uint32_t mbE1   = mbA + 32;

    if (tid == 0) {
        MBAR_INIT(mbA, 1);
        MBAR_INIT(mbF0, 1);
        MBAR_INIT(mbF1, 1);
        MBAR_INIT(mbE0, 8);
        MBAR_INIT(mbE1, 8);
    }
    __syncthreads();

    if (tid == 0) {
        MBAR_EXPECT_TX(mbA, A_BYTES);
        bulk_g2s(sbA, g_e0p + (size_t)row0 * LDK2, A_BYTES, mbA);
        MBAR_EXPECT_TX(mbF0, TILE_BYTES);
        bulk_g2s(sbB0, g_c0p, TILE_BYTES, mbF0);
    }

    uint32_t a_addr[2];
#pragma unroll
    for (int mi = 0; mi < 2; ++mi)
        a_addr[mi] = sbA + ((warp_m * 32 + mi * 16 + (lane & 15)) * LDK2 + (lane >> 4) * 8) * 2;
    uint32_t b_addr[2];
#pragma unroll
    for (int njp = 0; njp < 2; ++njp)
        b_addr[njp] = sbB0 + ((warp_n * 32 + njp * 16 + (lane & 7) + ((lane >> 4) << 3)) * LDK2
                              + ((lane >> 3) & 1) * 8) * 2;

    float v1[4], v2[4], v3[4], v4[4];
    int   i1[4], i2[4], i3[4];
#pragma unroll
    for (int r = 0; r < 4; ++r) {
        v1[r] = v2[r] = v3[r] = v4[r] = -INFINITY;
        i1[r] = i2[r] = i3[r] = 0;
    }

    const int cq = (lane & 3) * 2;

    MBAR_WAIT(mbA, 0);

    for (int t = 0, kt = 0; t < 128; ++t, kt += 128) {
        const uint32_t bufo = (uint32_t)(t & 1) * TILE_BYTES;

        // producer: issue fill for tile t+1 into the other buffer
        if (tid == 0 && t < 127) {
            const int tn = t + 1;
            const int bn = tn & 1;
            const int f  = tn >> 1;               // fill count for that buffer
            uint32_t mbE = bn ? mbE1 : mbE0;
            uint32_t mbF = bn ? mbF1 : mbF0;
            if (f > 0) MBAR_WAIT(mbE, (f & 1) ^ 1);   // all 8 warps done with prior use
            MBAR_EXPECT_TX(mbF, TILE_BYTES);
            bulk_g2s(sbB0 + (uint32_t)bn * TILE_BYTES,
                     g_c0p + (size_t)(kt + 128) * LDK2, TILE_BYTES, mbF);
        }

        // consumer: wait current tile (buffer t&1, use t>>1)
        MBAR_WAIT((t & 1) ? mbF1 : mbF0, (t >> 1) & 1);

        // nc from the smem row padding (broadcast LDS, conflict-free)
        float nc[8];
#pragma unroll
        for (int nj = 0; nj < 4; ++nj) {
#pragma unroll
            for (int q = 0; q < 2; ++q) {
                uint32_t addr = sbB0 - A_BYTES + SB_A;   // dummy to quiet compiler (unused)
                (void)addr;
                asm volatile("ld.shared.f32 %0, [%1];"
                    : "=f"(nc[nj * 2 + q])
                    : "r"(sbB0 + bufo + (uint32_t)(warp_n * 32 + nj * 8 + cq + q) * (LDK2 * 2) + 256));
            }
        }

        float acc[2][4][4];
#pragma unroll
        for (int mi = 0; mi < 2; ++mi)
#pragma unroll
            for (int nj = 0; nj < 4; ++nj)
#pragma unroll
                for (int k = 0; k < 4; ++k) acc[mi][nj][k] = 0.f;

#pragma unroll
        for (int s = 0; s < 8; ++s) {
            uint32_t af[2][4], bf[2][4];
#pragma unroll
            for (int mi = 0; mi < 2; ++mi) ldsm_x4(af[mi], a_addr[mi] + s * 32);
#pragma unroll
            for (int njp = 0; njp < 2; ++njp) ldsm_x4(bf[njp], b_addr[njp] + bufo + s * 32);
#pragma unroll
            for (int mi = 0; mi < 2; ++mi)
#pragma unroll
                for (int nj = 0; nj < 4; ++nj)
                    mma_bf16(acc[mi][nj], af[mi], bf[nj >> 1] + (nj & 1) * 2);
        }

        // done reading this buffer: one arrive per warp (count = 8)
        if (lane == 0) MBAR_ARRIVE((t & 1) ? mbE1 : mbE0);

        // epilogue: add nc, max-of-8 quick reject, rare insert
#pragma unroll
        for (int mi = 0; mi < 2; ++mi) {
#pragma unroll
            for (int h = 0; h < 2; ++h) {
                const int ri = mi * 2 + h;
                float s0 = acc[mi][0][h * 2]     + nc[0];
                float s1 = acc[mi][0][h * 2 + 1] + nc[1];
                float s2 = acc[mi][1][h * 2]     + nc[2];
                float s3 = acc[mi][1][h * 2 + 1] + nc[3];
                float s4 = acc[mi][2][h * 2]     + nc[4];
                float s5 = acc[mi][2][h * 2 + 1] + nc[5];
                float s6 = acc[mi][3][h * 2]     + nc[6];
                float s7 = acc[mi][3][h * 2 + 1] + nc[7];
                float m8 = fmaxf(fmaxf(fmaxf(s0, s1), fmaxf(s2, s3)),
                                 fmaxf(fmaxf(s4, s5), fmaxf(s6, s7)));
                if (m8 > v4[ri]) {
                    float sv[8] = {s0, s1, s2, s3, s4, s5, s6, s7};
#pragma unroll
                    for (int j = 0; j < 8; ++j) {
                        float v = sv[j];
                        if (v > v4[ri]) {
                            int idx = kt + warp_n * 32 + (j >> 1) * 8 + cq + (j & 1);
                            if (v > v1[ri]) {
                                v4[ri] = v3[ri]; v3[ri] = v2[ri]; i3[ri] = i2[ri];
                                v2[ri] = v1[ri]; i2[ri] = i1[ri];
                                v1[ri] = v; i1[ri] = idx;
                            } else if (v > v2[ri]) {
                                v4[ri] = v3[ri]; v3[ri] = v2[ri]; i3[ri] = i2[ri];
                                v2[ri] = v; i2[ri] = idx;
                            } else if (v > v3[ri]) {
                                v4[ri] = v3[ri]; v3[ri] = v; i3[ri] = idx;
                            } else {
                                v4[ri] = v;
                            }
                        }
                    }
                }
            }
        }
    }

    // write candidates + v4; reduce smax
    const int slot = warp_n * 4 + (lane & 3);
#pragma unroll
    for (int ri = 0; ri < 4; ++ri) {
        int mi = ri >> 1, h = ri & 1;
        int lrow = warp_m * 32 + mi * 16 + (lane >> 2) + h * 8;
        size_t row = (size_t)(row0 + lrow);
        g_cand_val[row * 48 + slot * 3]     = v1[ri];
        g_cand_idx[row * 48 + slot * 3]     = i1[ri];
        g_cand_val[row * 48 + slot * 3 + 1] = v2[ri];
        g_cand_idx[row * 48 + slot * 3 + 1] = i2[ri];
        g_cand_val[row * 48 + slot * 3 + 2] = v3[ri];
        g_cand_idx[row * 48 + slot * 3 + 2] = i3[ri];
        g_fourth[row * 16 + slot] = v4[ri];
        redsm[lrow * 16 + slot] = v1[ri];
    }
    __syncthreads();
    if (tid < 64) {
        float m = redsm[tid * 16];
#pragma unroll
        for (int w = 1; w < 16; ++w) m = fmaxf(m, redsm[tid * 16 + w]);
        g_smax[row0 + tid] = m;
    }
}

// ---------------- exact rescore (warp per row) ----------------
__global__ void rescore_kernel(const float* __restrict__ CB)
{
    const int r = blockIdx.x * 4 + (threadIdx.x >> 5);
    const int lane = threadIdx.x & 31;

    float delta = sqrtf(g_en2[r]) * sqrtf(g_Rmax2) + sqrtf(g_dn2[r]) * sqrtf(g_Nmax2);
    float thresh = g_smax[r] - 1.05f * delta - 1e-4f;

    float th = (lane < 16) ? g_fourth[(size_t)r * 16 + lane] : -INFINITY;
    bool flag = __ballot_sync(0xffffffff, th >= thresh) != 0;

    const float4 e4 = ((const float4*)(g_enc + (size_t)r * 128))[lane];

    float bs = -INFINITY;
    int bi = 0x7fffffff;

    if (!flag) {
        for (int s = 0; s < 48; ++s) {
            float v = g_cand_val[(size_t)r * 48 + s];
            if (v >= thresh) {
                int idx = g_cand_idx[(size_t)r * 48 + s];
                float4 c4 = ((const float4*)(CB + (size_t)idx * 128))[lane];
                float d = e4.x*c4.x + e4.y*c4.y + e4.z*c4.z + e4.w*c4.w;
#pragma unroll
                for (int o = 16; o > 0; o >>= 1) d += __shfl_xor_sync(0xffffffff, d, o);
                float sx = d + g_negc2[idx];
                if (sx > bs || (sx == bs && idx < bi)) { bs = sx; bi = idx; }
            }
        }
    } else {
        for (int k = 0; k < Kn; ++k) {
            float4 c4 = ((const float4*)(CB + (size_t)k * 128))[lane];
            float d = e4.x*c4.x + e4.y*c4.y + e4.z*c4.z + e4.w*c4.w;
#pragma unroll
            for (int o = 16; o > 0; o >>= 1) d += __shfl_xor_sync(0xffffffff, d, o);
            float sx = d + g_negc2[k];
            if (sx > bs) { bs = sx; bi = k; }
        }
    }
    if (lane == 0) g_idx[r] = bi;
}

// ---------------- decoder ----------------
__global__ void decoder_kernel(const float* __restrict__ C,
                               const float* __restrict__ W3, const float* __restrict__ b3,
                               const float* __restrict__ g2, const float* __restrict__ be2,
                               const float* __restrict__ W4, const float* __restrict__ b4,
                               const float* __restrict__ X)
{
    extern __shared__ float sm[];
    float* Qs = sm;
    float* Hs = sm + 32 * Zn;
    float* ep = Hs + 32 * Hn;
    const int tid = threadIdx.x;
    const int row0 = blockIdx.x * 32;

    for (int i = tid; i < 32 * 32; i += 256) {
        int r = i >> 5, d4 = i & 31;
        int code = g_idx[row0 + r];
        ((float4*)Qs)[r * 32 + d4] = ((const float4*)C)[(size_t)code * 32 + d4];
    }
    __syncthreads();

    {
        const float4* Qs4 = (const float4*)Qs;
        float acc[32];
#pragma unroll
        for (int r = 0; r < 32; ++r) acc[r] = 0.f;
        const int col = tid;
        for (int d = 0; d < Zn; d += 4) {
            float w0 = W3[(d + 0) * Hn + col];
            float w1 = W3[(d + 1) * Hn + col];
            float w2 = W3[(d + 2) * Hn + col];
            float w3 = W3[(d + 3) * Hn + col];
#pragma unroll
            for (int r = 0; r < 32; ++r) {
                float4 q = Qs4[(r * Zn + d) >> 2];
                acc[r] = fmaf(q.x, w0, acc[r]);
                acc[r] = fmaf(q.y, w1, acc[r]);
                acc[r] = fmaf(q.z, w2, acc[r]);
                acc[r] = fmaf(q.w, w3, acc[r]);
            }
        }
        float bb = b3[col];
#pragma unroll
        for (int r = 0; r < 32; ++r) Hs[r * Hn + col] = acc[r] + bb;
    }
    __syncthreads();

    {
        const int warp = tid >> 5, lane = tid & 31;
        for (int rr = 0; rr < 4; ++rr) {
            int r = warp + rr * 8;
            float s = 0.f, s2 = 0.f;
#pragma unroll
            for (int j = 0; j < 8; ++j) {
                float v = Hs[r * Hn + lane + j * 32];
                s += v; s2 += v * v;
            }
#pragma unroll
            for (int o = 16; o > 0; o >>= 1) {
                s  += __shfl_xor_sync(0xffffffff, s,  o);
                s2 += __shfl_xor_sync(0xffffffff, s2, o);
            }
            float mu  = s * (1.f / Hn);
            float var = s2 * (1.f / Hn) - mu * mu;
            float inv = rsqrtf(var + 1e-5f);
#pragma unroll
            for (int j = 0; j < 8; ++j) {
                int c = lane + j * 32;
                float v = (Hs[r * Hn + c] - mu) * inv * g2[c] + be2[c];
                Hs[r * Hn + c] = 0.5f * v * (1.f + erff(v * 0.70710678118654752f));
            }
        }
    }
    __syncthreads();

    float aA[32], aB[32];
#pragma unroll
    for (int r = 0; r < 32; ++r) { aA[r] = 0.f; aB[r] = 0.f; }
    {
        const float4* Hs4 = (const float4*)Hs;
        for (int d = 0; d < Hn; d += 4) {
            float wa0 = W4[(d + 0) * Dn + tid];
            float wa1 = W4[(d + 1) * Dn + tid];
            float wa2 = W4[(d + 2) * Dn + tid];
            float wa3 = W4[(d + 3) * Dn + tid];
            float wb0 = W4[(d + 0) * Dn + tid + 256];
            float wb1 = W4[(d + 1) * Dn + tid + 256];
            float wb2 = W4[(d + 2) * Dn + tid + 256];
            float wb3 = W4[(d + 3) * Dn + tid + 256];
#pragma unroll
            for (int r = 0; r < 32; ++r) {
                float4 h = Hs4[(r * Hn + d) >> 2];
                aA[r] = fmaf(h.x, wa0, aA[r]);
                aA[r] = fmaf(h.y, wa1, aA[r]);
                aA[r] = fmaf(h.z, wa2, aA[r]);
                aA[r] = fmaf(h.w, wa3, aA[r]);
                aB[r] = fmaf(h.x, wb0, aB[r]);
                aB[r] = fmaf(h.y, wb1, aB[r]);
                aB[r] = fmaf(h.z, wb2, aB[r]);
                aB[r] = fmaf(h.w, wb3, aB[r]);
            }
        }
    }

    {
        const int warp = tid >> 5, lane = tid & 31;
        float b4a = b4[tid], b4b = b4[tid + 256];
        for (int r = 0; r < 32; ++r) {
            float f1 = X[(size_t)(row0 + r) * Dn + tid];
            float f2 = X[(size_t)(row0 + r) * Dn + tid + 256];
            float d1 = aA[r] + b4a - f1;
            float d2 = aB[r] + b4b - f2;
            float e = d1 * d1 + d2 * d2;
#pragma unroll
            for (int o = 16; o > 0; o >>= 1) e += __shfl_xor_sync(0xffffffff, e, o);
            if (lane == 0) ep[r * 8 + warp] = e;
        }
        __syncthreads();
        if (tid < 32) {
            float s = 0.f;
#pragma unroll
            for (int w = 0; w < 8; ++w) s += ep[tid * 8 + w];
            g_err[row0 + tid] = s * (1.f / Dn);
        }
    }
}

// ---------------- global mean ----------------
__global__ void reduce_kernel()
{
    __shared__ float s[256];
    int tid = threadIdx.x;
    float a = 0.f;
    for (int i = tid; i < Bn; i += 256) a += g_err[i];
    s[tid] = a;
    __syncthreads();
    for (int o = 128; o > 0; o >>= 1) {
        if (tid < o) s[tid] += s[tid + o];
        __syncthreads();
    }
    if (tid == 0) g_sum = s[0];
}

// ---------------- MDL + output ----------------
__global__ void final_kernel(float* __restrict__ out)
{
    int i = blockIdx.x * 256 + threadIdx.x;
    float scale = g_sum * (1.f / Bn) + 1e-8f;
    float err = g_err[i];
    float eb = (fabsf(err) / scale + logf(2.f * scale)) * 1.4426950408889634f;
    float tb = 14.f + eb;
    out[i]          = err;
    out[Bn + i]     = (Dn * 32.f) / tb;
    out[2 * Bn + i] = tb;
    out[3 * Bn + i] = (float)g_idx[i];
}

// ---------------- launch ----------------
extern "C" void kernel_launch(void* const* d_in, const int* in_sizes, int n_in,
                              void* d_out, int out_size)
{
    const float* X   = (const float*)d_in[0];
    const float* W1  = (const float*)d_in[1];
    const float* b1  = (const float*)d_in[2];
    const float* g1  = (const float*)d_in[3];
    const float* be1 = (const float*)d_in[4];
    const float* W2  = (const float*)d_in[5];
    const float* b2  = (const float*)d_in[6];
    const float* CB  = (const float*)d_in[7];
    const float* W3  = (const float*)d_in[8];
    const float* b3  = (const float*)d_in[9];
    const float* g2  = (const float*)d_in[10];
    const float* be2 = (const float*)d_in[11];
    const float* W4  = (const float*)d_in[12];
    const float* b4  = (const float*)d_in[13];
    float* out = (float*)d_out;

    cudaFuncSetAttribute(encoder_kernel,     cudaFuncAttributeMaxDynamicSharedMemorySize, 98304);
    cudaFuncSetAttribute(dist_coarse_kernel, cudaFuncAttributeMaxDynamicSharedMemorySize, DSM2_TOT);
    cudaFuncSetAttribute(decoder_kernel,     cudaFuncAttributeMaxDynamicSharedMemorySize, 50176);

    c0split_kernel<<<Kn / 8, 256>>>(CB);
    encoder_kernel<<<Bn / 32, 256, 98304>>>(X, W1, b1, g1, be1, W2, b2);
    enorm_kernel<<<Bn / 8, 256>>>();
    dist_coarse_kernel<<<Bn / 64, 256, DSM2_TOT>>>();
    rescore_kernel<<<Bn / 4, 128>>>(CB);
    decoder_kernel<<<Bn / 32, 256, 50176>>>(CB, W3, b3, g2, be2, W4, b4, X);
    reduce_kernel<<<1, 256>>>();
    final_kernel<<<Bn / 256, 256>>>(out);
}

// round 11
// speedup vs baseline: 1.4071x; 1.1110x over previous
#include <cuda_runtime.h>
#include <cuda_bf16.h>
#include <math.h>
#include <stdint.h>

#define Bn 16384
#define Dn 512
#define Kn 16384
#define Hn 256
#define Zn 128
#define LDK2 136                     // padded row stride in bf16 (272B); bytes 256..259 carry -0.5||c||^2

// ---------------- scratch ----------------
__device__ __align__(16) float g_enc[(size_t)Bn * Zn];
__device__ __align__(16) __nv_bfloat16 g_e0p[(size_t)Bn * LDK2];
__device__ __align__(16) __nv_bfloat16 g_c0p[(size_t)Kn * LDK2];
__device__ float g_negc2[Kn];
__device__ float g_en2[Bn];
__device__ float g_dn2[Bn];
__device__ float g_Rmax2;
__device__ float g_Nmax2;
__device__ float g_smax[Bn];
__device__ float g_cand_val[(size_t)Bn * 48];
__device__ int   g_cand_idx[(size_t)Bn * 48];
__device__ float g_fourth[(size_t)Bn * 16];
__device__ int   g_idx[Bn];
__device__ float g_err[Bn];
__device__ float g_sum;
// W4 pre-packed B-fragments: [s(16)][j(64)][p(2)][lane(32)] of uint2
__device__ __align__(16) uint2 g_W4f[16 * 64 * 2 * 32];

// ---------------- helpers ----------------
__device__ __forceinline__ uint32_t smem_u32(const void* p) {
    uint32_t a;
    asm("{ .reg .u64 t; cvta.to.shared.u64 t, %1; cvt.u32.u64 %0, t; }" : "=r"(a) : "l"(p));
    return a;
}
__device__ __forceinline__ void ldsm_x4(uint32_t r[4], uint32_t addr) {
    asm volatile("ldmatrix.sync.aligned.m8n8.x4.shared.b16 {%0,%1,%2,%3}, [%4];"
        : "=r"(r[0]), "=r"(r[1]), "=r"(r[2]), "=r"(r[3]) : "r"(addr));
}
__device__ __forceinline__ void mma_bf16(float d[4], const uint32_t a[4], const uint32_t b[2]) {
    asm volatile("mma.sync.aligned.m16n8k16.row.col.f32.bf16.bf16.f32 "
        "{%0,%1,%2,%3}, {%4,%5,%6,%7}, {%8,%9}, {%0,%1,%2,%3};"
        : "+f"(d[0]), "+f"(d[1]), "+f"(d[2]), "+f"(d[3])
        : "r"(a[0]), "r"(a[1]), "r"(a[2]), "r"(a[3]), "r"(b[0]), "r"(b[1]));
}
__device__ __forceinline__ uint32_t pack_bf16(float a, float b) {
    __nv_bfloat162 t = __floats2bfloat162_rn(a, b);
    return *(uint32_t*)&t;
}
__device__ __forceinline__ void bulk_g2s(uint32_t dst, const void* src, uint32_t bytes, uint32_t mbar) {
    asm volatile("cp.async.bulk.shared::cluster.global.mbarrier::complete_tx::bytes [%0], [%1], %2, [%3];"
        :: "r"(dst), "l"(src), "r"(bytes), "r"(mbar) : "memory");
}
#define MBAR_INIT(mb, c) \
    asm volatile("mbarrier.init.shared.b64 [%0], %1;" :: "r"((uint32_t)(mb)), "r"((uint32_t)(c)) : "memory")
#define MBAR_EXPECT_TX(mb, n) \
    asm volatile("mbarrier.arrive.expect_tx.shared.b64 _, [%0], %1;" :: "r"((uint32_t)(mb)), "r"((uint32_t)(n)) : "memory")
#define MBAR_ARRIVE(mb) \
    asm volatile("mbarrier.arrive.shared.b64 _, [%0];" :: "r"((uint32_t)(mb)) : "memory")
#define MBAR_WAIT(mb, par) do { \
    uint32_t _m = (uint32_t)(mb); uint32_t _p = (uint32_t)(par); uint32_t _d; \
    asm volatile("{\n\t.reg .pred p;\n\t" \
        "mbarrier.try_wait.parity.acquire.cta.shared::cta.b64 p, [%1], %2;\n\t" \
        "selp.b32 %0, 1, 0, p;\n\t}" : "=r"(_d) : "r"(_m), "r"(_p) : "memory"); \
    if (!_d) { \
        asm volatile("{\n\t.reg .pred P1;\n\t" \
            "WL_%=:\n\t" \
            "mbarrier.try_wait.parity.acquire.cta.shared::cta.b64 P1, [%0], %1, 0x989680;\n\t" \
            "@P1 bra.uni WD_%=;\n\tbra.uni WL_%=;\n\tWD_%=:\n\t}" \
            :: "r"(_m), "r"(_p) : "memory"); \
    } } while (0)

// ---------------- encoder ----------------
__global__ void encoder_kernel(const float* __restrict__ X,
                               const float* __restrict__ W1, const float* __restrict__ b1,
                               const float* __restrict__ g1, const float* __restrict__ be1,
                               const float* __restrict__ W2, const float* __restrict__ b2)
{
    extern __shared__ float sm[];
    float* Xs = sm;
    float* Hs = sm + 32 * Dn;
    const int tid = threadIdx.x;
    const int row0 = blockIdx.x * 32;

    {
        const float4* Xg = (const float4*)(X + (size_t)row0 * Dn);
        float4* Xs4 = (float4*)Xs;
        for (int i = tid; i < 32 * Dn / 4; i += 256) Xs4[i] = Xg[i];
    }
    __syncthreads();

    const float4* Xs4 = (const float4*)Xs;
    float acc[32];
#pragma unroll
    for (int r = 0; r < 32; ++r) acc[r] = 0.f;
    const int col = tid;
    for (int d = 0; d < Dn; d += 4) {
        float w0 = W1[(d + 0) * Hn + col];
        float w1 = W1[(d + 1) * Hn + col];
        float w2 = W1[(d + 2) * Hn + col];
        float w3 = W1[(d + 3) * Hn + col];
#pragma unroll
        for (int r = 0; r < 32; ++r) {
            float4 x = Xs4[(r * Dn + d) >> 2];
            acc[r] = fmaf(x.x, w0, acc[r]);
            acc[r] = fmaf(x.y, w1, acc[r]);
            acc[r] = fmaf(x.z, w2, acc[r]);
            acc[r] = fmaf(x.w, w3, acc[r]);
        }
    }
    {
        float bb = b1[col];
#pragma unroll
        for (int r = 0; r < 32; ++r) Hs[r * Hn + col] = acc[r] + bb;
    }
    __syncthreads();

    {
        const int warp = tid >> 5, lane = tid & 31;
        for (int rr = 0; rr < 4; ++rr) {
            int r = warp + rr * 8;
            float s = 0.f, s2 = 0.f;
#pragma unroll
            for (int j = 0; j < 8; ++j) {
                float v = Hs[r * Hn + lane + j * 32];
                s += v; s2 += v * v;
            }
#pragma unroll
            for (int o = 16; o > 0; o >>= 1) {
                s  += __shfl_xor_sync(0xffffffff, s,  o);
                s2 += __shfl_xor_sync(0xffffffff, s2, o);
            }
            float mu  = s * (1.f / Hn);
            float var = s2 * (1.f / Hn) - mu * mu;
            float inv = rsqrtf(var + 1e-5f);
#pragma unroll
            for (int j = 0; j < 8; ++j) {
                int c = lane + j * 32;
                float v = (Hs[r * Hn + c] - mu) * inv * g1[c] + be1[c];
                Hs[r * Hn + c] = 0.5f * v * (1.f + erff(v * 0.70710678118654752f));
            }
        }
    }
    __syncthreads();

    {
        const float4* Hs4 = (const float4*)Hs;
        const int c2 = tid & 127;
        const int rbase = (tid >> 7) * 16;
        float a2[16];
#pragma unroll
        for (int r = 0; r < 16; ++r) a2[r] = 0.f;
        for (int d = 0; d < Hn; d += 4) {
            float w0 = W2[(d + 0) * Zn + c2];
            float w1 = W2[(d + 1) * Zn + c2];
            float w2 = W2[(d + 2) * Zn + c2];
            float w3 = W2[(d + 3) * Zn + c2];
#pragma unroll
            for (int r = 0; r < 16; ++r) {
                float4 h = Hs4[((rbase + r) * Hn + d) >> 2];
                a2[r] = fmaf(h.x, w0, a2[r]);
                a2[r] = fmaf(h.y, w1, a2[r]);
                a2[r] = fmaf(h.z, w2, a2[r]);
                a2[r] = fmaf(h.w, w3, a2[r]);
            }
        }
        float bb = b2[c2];
#pragma unroll
        for (int r = 0; r < 16; ++r)
            g_enc[(size_t)(row0 + rbase + r) * Zn + c2] = a2[r] + bb;
    }
}

// ---------------- per-row e0 (padded) + norms ----------------
__global__ void enorm_kernel()
{
    int gw = (blockIdx.x * 256 + threadIdx.x) >> 5;
    int lane = threadIdx.x & 31;
    const float4 e4 = ((const float4*)(g_enc + (size_t)gw * 128))[lane];
    float e0x = __bfloat162float(__float2bfloat16(e4.x));
    float e0y = __bfloat162float(__float2bfloat16(e4.y));
    float e0z = __bfloat162float(__float2bfloat16(e4.z));
    float e0w = __bfloat162float(__float2bfloat16(e4.w));
    *(uint2*)(g_e0p + (size_t)gw * LDK2 + lane * 4) =
        make_uint2(pack_bf16(e4.x, e4.y), pack_bf16(e4.z, e4.w));
    float en2 = e4.x*e4.x + e4.y*e4.y + e4.z*e4.z + e4.w*e4.w;
    float dx = e4.x - e0x, dy = e4.y - e0y, dz = e4.z - e0z, dw = e4.w - e0w;
    float dn2 = dx*dx + dy*dy + dz*dz + dw*dw;
#pragma unroll
    for (int o = 16; o > 0; o >>= 1) {
        en2 += __shfl_xor_sync(0xffffffff, en2, o);
        dn2 += __shfl_xor_sync(0xffffffff, dn2, o);
    }
    if (lane == 0) { g_en2[gw] = en2; g_dn2[gw] = dn2; }
}

// ---------------- codebook prep (padded; nc stashed in row padding) ----------------
__global__ void c0split_kernel(const float* __restrict__ C)
{
    int code = (blockIdx.x * 256 + threadIdx.x) >> 5;
    int lane = threadIdx.x & 31;
    const float4 c4 = ((const float4*)(C + (size_t)code * 128))[lane];
    float c0x = __bfloat162float(__float2bfloat16(c4.x));
    float c0y = __bfloat162float(__float2bfloat16(c4.y));
    float c0z = __bfloat162float(__float2bfloat16(c4.z));
    float c0w = __bfloat162float(__float2bfloat16(c4.w));
    *(uint2*)(g_c0p + (size_t)code * LDK2 + lane * 4) =
        make_uint2(pack_bf16(c4.x, c4.y), pack_bf16(c4.z, c4.w));
    float c2 = c4.x*c4.x + c4.y*c4.y + c4.z*c4.z + c4.w*c4.w;
    float n2 = c0x*c0x + c0y*c0y + c0z*c0z + c0w*c0w;
    float dx = c4.x - c0x, dy = c4.y - c0y, dz = c4.z - c0z, dw = c4.w - c0w;
    float r2 = dx*dx + dy*dy + dz*dz + dw*dw;
#pragma unroll
    for (int o = 16; o > 0; o >>= 1) {
        c2 += __shfl_xor_sync(0xffffffff, c2, o);
        n2 += __shfl_xor_sync(0xffffffff, n2, o);
        r2 += __shfl_xor_sync(0xffffffff, r2, o);
    }
    if (lane == 0) {
        float nc = -0.5f * c2;
        g_negc2[code] = nc;
        *(float*)((char*)g_c0p + (size_t)code * (LDK2 * 2) + 256) = nc;
        atomicMax((int*)&g_Rmax2, __float_as_int(r2));
        atomicMax((int*)&g_Nmax2, __float_as_int(n2));
    }
}

// ---------------- W4 fragment pre-pack (2-way bf16 split, B-frag order) ----------------
// layout: g_W4f[((s*64 + j)*2 + p)*32 + lane] = uint2{reg0, reg1}
// reg r = pack(Wp[k][n], Wp[k+1][n]); k = s*16 + (lane&3)*2 + r*8; n = j*8 + (lane>>2)
__global__ void w4split_kernel(const float* __restrict__ W4)
{
    int i = blockIdx.x * 256 + threadIdx.x;      // 65536 total
    int lane = i & 31;
    int p = (i >> 5) & 1;
    int j = (i >> 6) & 63;
    int s = i >> 12;
    int n = j * 8 + (lane >> 2);
    uint32_t regs[2];
#pragma unroll
    for (int r = 0; r < 2; ++r) {
        int k = s * 16 + (lane & 3) * 2 + r * 8;
        float wa = W4[(size_t)k * Dn + n];
        float wb = W4[(size_t)(k + 1) * Dn + n];
        float va, vb;
        if (p == 0) {
            va = __bfloat162float(__float2bfloat16(wa));
            vb = __bfloat162float(__float2bfloat16(wb));
        } else {
            va = wa - __bfloat162float(__float2bfloat16(wa));
            vb = wb - __bfloat162float(__float2bfloat16(wb));
        }
        regs[r] = pack_bf16(va, vb);
    }
    g_W4f[i] = make_uint2(regs[0], regs[1]);
}

// ---------------- coarse distance: mbarrier ring (unchanged from R10) ----------------
#define A_BYTES (64 * LDK2 * 2)
#define TILE_BYTES (128 * LDK2 * 2)
#define SB_A 0
#define SB_B0 A_BYTES
#define SB_MBAR (A_BYTES + 2 * TILE_BYTES)
#define SB_RED (SB_MBAR + 64)
#define DSM2_TOT (SB_RED + 64 * 16 * 4)

__global__ __launch_bounds__(256, 2) void dist_coarse_kernel()
{
    extern __shared__ char smem[];
    float* redsm = (float*)(smem + SB_RED);

    const int tid  = threadIdx.x;
    const int lane = tid & 31;
    const int wid  = tid >> 5;
    const int warp_m = wid >> 2;
    const int warp_n = wid & 3;
    const int row0 = blockIdx.x * 64;

    const uint32_t sbA    = smem_u32(smem) + SB_A;
    const uint32_t sbB0   = smem_u32(smem) + SB_B0;
    const uint32_t mbA    = smem_u32(smem) + SB_MBAR;
    const uint32_t mbF0   = mbA + 8;
    const uint32_t mbF1   = mbA + 16;
    const uint32_t mbE0   = mbA + 24;
    const uint32_t mbE1   = mbA + 32;

    if (tid == 0) {
        MBAR_INIT(mbA, 1);
        MBAR_INIT(mbF0, 1);
        MBAR_INIT(mbF1, 1);
        MBAR_INIT(mbE0, 8);
        MBAR_INIT(mbE1, 8);
    }
    __syncthreads();

    if (tid == 0) {
        MBAR_EXPECT_TX(mbA, A_BYTES);
        bulk_g2s(sbA, g_e0p + (size_t)row0 * LDK2, A_BYTES, mbA);
        MBAR_EXPECT_TX(mbF0, TILE_BYTES);
        bulk_g2s(sbB0, g_c0p, TILE_BYTES, mbF0);
    }

    uint32_t a_addr[2];
#pragma unroll
    for (int mi = 0; mi < 2; ++mi)
        a_addr[mi] = sbA + ((warp_m * 32 + mi * 16 + (lane & 15)) * LDK2 + (lane >> 4) * 8) * 2;
    uint32_t b_addr[2];
#pragma unroll
    for (int njp = 0; njp < 2; ++njp)
        b_addr[njp] = sbB0 + ((warp_n * 32 + njp * 16 + (lane & 7) + ((lane >> 4) << 3)) * LDK2
                              + ((lane >> 3) & 1) * 8) * 2;

    float v1[4], v2[4], v3[4], v4[4];
    int   i1[4], i2[4], i3[4];
#pragma unroll
    for (int r = 0; r < 4; ++r) {
        v1[r] = v2[r] = v3[r] = v4[r] = -INFINITY;
        i1[r] = i2[r] = i3[r] = 0;
    }

    const int cq = (lane & 3) * 2;

    MBAR_WAIT(mbA, 0);

    for (int t = 0, kt = 0; t < 128; ++t, kt += 128) {
        const uint32_t bufo = (uint32_t)(t & 1) * TILE_BYTES;

        if (tid == 0 && t < 127) {
            const int tn = t + 1;
            const int bn = tn & 1;
            const int f  = tn >> 1;
            uint32_t mbE = bn ? mbE1 : mbE0;
            uint32_t mbF = bn ? mbF1 : mbF0;
            if (f > 0) MBAR_WAIT(mbE, (f & 1) ^ 1);
            MBAR_EXPECT_TX(mbF, TILE_BYTES);
            bulk_g2s(sbB0 + (uint32_t)bn * TILE_BYTES,
                     g_c0p + (size_t)(kt + 128) * LDK2, TILE_BYTES, mbF);
        }

        MBAR_WAIT((t & 1) ? mbF1 : mbF0, (t >> 1) & 1);

        float nc[8];
#pragma unroll
        for (int nj = 0; nj < 4; ++nj) {
#pragma unroll
            for (int q = 0; q < 2; ++q) {
                asm volatile("ld.shared.f32 %0, [%1];"
                    : "=f"(nc[nj * 2 + q])
                    : "r"(sbB0 + bufo + (uint32_t)(warp_n * 32 + nj * 8 + cq + q) * (LDK2 * 2) + 256));
            }
        }

        float acc[2][4][4];
#pragma unroll
        for (int mi = 0; mi < 2; ++mi)
#pragma unroll
            for (int nj = 0; nj < 4; ++nj)
#pragma unroll
                for (int k = 0; k < 4; ++k) acc[mi][nj][k] = 0.f;

#pragma unroll
        for (int s = 0; s < 8; ++s) {
            uint32_t af[2][4], bf[2][4];
#pragma unroll
            for (int mi = 0; mi < 2; ++mi) ldsm_x4(af[mi], a_addr[mi] + s * 32);
#pragma unroll
            for (int njp = 0; njp < 2; ++njp) ldsm_x4(bf[njp], b_addr[njp] + bufo + s * 32);
#pragma unroll
            for (int mi = 0; mi < 2; ++mi)
#pragma unroll
                for (int nj = 0; nj < 4; ++nj)
                    mma_bf16(acc[mi][nj], af[mi], bf[nj >> 1] + (nj & 1) * 2);
        }

        if (lane == 0) MBAR_ARRIVE((t & 1) ? mbE1 : mbE0);

#pragma unroll
        for (int mi = 0; mi < 2; ++mi) {
#pragma unroll
            for (int h = 0; h < 2; ++h) {
                const int ri = mi * 2 + h;
                float s0 = acc[mi][0][h * 2]     + nc[0];
                float s1 = acc[mi][0][h * 2 + 1] + nc[1];
                float s2 = acc[mi][1][h * 2]     + nc[2];
                float s3 = acc[mi][1][h * 2 + 1] + nc[3];
                float s4 = acc[mi][2][h * 2]     + nc[4];
                float s5 = acc[mi][2][h * 2 + 1] + nc[5];
                float s6 = acc[mi][3][h * 2]     + nc[6];
                float s7 = acc[mi][3][h * 2 + 1] + nc[7];
                float m8 = fmaxf(fmaxf(fmaxf(s0, s1), fmaxf(s2, s3)),
                                 fmaxf(fmaxf(s4, s5), fmaxf(s6, s7)));
                if (m8 > v4[ri]) {
                    float sv[8] = {s0, s1, s2, s3, s4, s5, s6, s7};
#pragma unroll
                    for (int j = 0; j < 8; ++j) {
                        float v = sv[j];
                        if (v > v4[ri]) {
                            int idx = kt + warp_n * 32 + (j >> 1) * 8 + cq + (j & 1);
                            if (v > v1[ri]) {
                                v4[ri] = v3[ri]; v3[ri] = v2[ri]; i3[ri] = i2[ri];
                                v2[ri] = v1[ri]; i2[ri] = i1[ri];
                                v1[ri] = v; i1[ri] = idx;
                            } else if (v > v2[ri]) {
                                v4[ri] = v3[ri]; v3[ri] = v2[ri]; i3[ri] = i2[ri];
                                v2[ri] = v; i2[ri] = idx;
                            } else if (v > v3[ri]) {
                                v4[ri] = v3[ri]; v3[ri] = v; i3[ri] = idx;
                            } else {
                                v4[ri] = v;
                            }
                        }
                    }
                }
            }
        }
    }

    const int slot = warp_n * 4 + (lane & 3);
#pragma unroll
    for (int ri = 0; ri < 4; ++ri) {
        int mi = ri >> 1, h = ri & 1;
        int lrow = warp_m * 32 + mi * 16 + (lane >> 2) + h * 8;
        size_t row = (size_t)(row0 + lrow);
        g_cand_val[row * 48 + slot * 3]     = v1[ri];
        g_cand_idx[row * 48 + slot * 3]     = i1[ri];
        g_cand_val[row * 48 + slot * 3 + 1] = v2[ri];
        g_cand_idx[row * 48 + slot * 3 + 1] = i2[ri];
        g_cand_val[row * 48 + slot * 3 + 2] = v3[ri];
        g_cand_idx[row * 48 + slot * 3 + 2] = i3[ri];
        g_fourth[row * 16 + slot] = v4[ri];
        redsm[lrow * 16 + slot] = v1[ri];
    }
    __syncthreads();
    if (tid < 64) {
        float m = redsm[tid * 16];
#pragma unroll
        for (int w = 1; w < 16; ++w) m = fmaxf(m, redsm[tid * 16 + w]);
        g_smax[row0 + tid] = m;
    }
}

// ---------------- exact rescore (warp per row) ----------------
__global__ void rescore_kernel(const float* __restrict__ CB)
{
    const int r = blockIdx.x * 4 + (threadIdx.x >> 5);
    const int lane = threadIdx.x & 31;

    float delta = sqrtf(g_en2[r]) * sqrtf(g_Rmax2) + sqrtf(g_dn2[r]) * sqrtf(g_Nmax2);
    float thresh = g_smax[r] - 1.05f * delta - 1e-4f;

    float th = (lane < 16) ? g_fourth[(size_t)r * 16 + lane] : -INFINITY;
    bool flag = __ballot_sync(0xffffffff, th >= thresh) != 0;

    const float4 e4 = ((const float4*)(g_enc + (size_t)r * 128))[lane];

    float bs = -INFINITY;
    int bi = 0x7fffffff;

    if (!flag) {
        for (int s = 0; s < 48; ++s) {
            float v = g_cand_val[(size_t)r * 48 + s];
            if (v >= thresh) {
                int idx = g_cand_idx[(size_t)r * 48 + s];
                float4 c4 = ((const float4*)(CB + (size_t)idx * 128))[lane];
                float d = e4.x*c4.x + e4.y*c4.y + e4.z*c4.z + e4.w*c4.w;
#pragma unroll
                for (int o = 16; o > 0; o >>= 1) d += __shfl_xor_sync(0xffffffff, d, o);
                float sx = d + g_negc2[idx];
                if (sx > bs || (sx == bs && idx < bi)) { bs = sx; bi = idx; }
            }
        }
    } else {
        for (int k = 0; k < Kn; ++k) {
            float4 c4 = ((const float4*)(CB + (size_t)k * 128))[lane];
            float d = e4.x*c4.x + e4.y*c4.y + e4.z*c4.z + e4.w*c4.w;
#pragma unroll
            for (int o = 16; o > 0; o >>= 1) d += __shfl_xor_sync(0xffffffff, d, o);
            float sx = d + g_negc2[k];
            if (sx > bs) { bs = sx; bi = k; }
        }
    }
    if (lane == 0) g_idx[r] = bi;
}

// ---------------- decoder: gather -> fp32 GEMM1 -> LN/GELU -> mma GEMM2 -> err ----------------
// smem: Qs 16KB | Hs 32KB | Hs0 16.5KB | Hs1 16.5KB | ep 1KB
#define DEC_HS0_OFF (32 * Zn + 32 * Hn)              // in floats: 12288
#define DEC_LDH 264                                  // bf16 stride (528B = 33*16, conflict-free)
#define DEC_SMEM (12288 * 4 + 2 * 32 * DEC_LDH * 2 + 32 * 8 * 4)   // 83968

__global__ void decoder_kernel(const float* __restrict__ C,
                               const float* __restrict__ W3, const float* __restrict__ b3,
                               const float* __restrict__ g2, const float* __restrict__ be2,
                               const float* __restrict__ b4,
                               const float* __restrict__ X)
{
    extern __shared__ float sm[];
    float* Qs = sm;
    float* Hs = sm + 32 * Zn;
    __nv_bfloat16* Hs0 = (__nv_bfloat16*)(sm + DEC_HS0_OFF);
    __nv_bfloat16* Hs1 = Hs0 + 32 * DEC_LDH;
    float* ep = (float*)(Hs1 + 32 * DEC_LDH);
    const int tid = threadIdx.x;
    const int lane = tid & 31;
    const int wid = tid >> 5;
    const int row0 = blockIdx.x * 32;

    for (int i = tid; i < 32 * 32; i += 256) {
        int r = i >> 5, d4 = i & 31;
        int code = g_idx[row0 + r];
        ((float4*)Qs)[r * 32 + d4] = ((const float4*)C)[(size_t)code * 32 + d4];
    }
    __syncthreads();

    // fp32 GEMM1: Q[32x128] @ W3[128x256]
    {
        const float4* Qs4 = (const float4*)Qs;
        float acc[32];
#pragma unroll
        for (int r = 0; r < 32; ++r) acc[r] = 0.f;
        const int col = tid;
        for (int d = 0; d < Zn; d += 4) {
            float w0 = W3[(d + 0) * Hn + col];
            float w1 = W3[(d + 1) * Hn + col];
            float w2 = W3[(d + 2) * Hn + col];
            float w3 = W3[(d + 3) * Hn + col];
#pragma unroll
            for (int r = 0; r < 32; ++r) {
                float4 q = Qs4[(r * Zn + d) >> 2];
                acc[r] = fmaf(q.x, w0, acc[r]);
                acc[r] = fmaf(q.y, w1, acc[r]);
                acc[r] = fmaf(q.z, w2, acc[r]);
                acc[r] = fmaf(q.w, w3, acc[r]);
            }
        }
        float bb = b3[col];
#pragma unroll
        for (int r = 0; r < 32; ++r) Hs[r * Hn + col] = acc[r] + bb;
    }
    __syncthreads();

    // LN + GELU
    {
        for (int rr = 0; rr < 4; ++rr) {
            int r = wid + rr * 8;
            float s = 0.f, s2 = 0.f;
#pragma unroll
            for (int j = 0; j < 8; ++j) {
                float v = Hs[r * Hn + lane + j * 32];
                s += v; s2 += v * v;
            }
#pragma unroll
            for (int o = 16; o > 0; o >>= 1) {
                s  += __shfl_xor_sync(0xffffffff, s,  o);
                s2 += __shfl_xor_sync(0xffffffff, s2, o);
            }
            float mu  = s * (1.f / Hn);
            float var = s2 * (1.f / Hn) - mu * mu;
            float inv = rsqrtf(var + 1e-5f);
#pragma unroll
            for (int j = 0; j < 8; ++j) {
                int c = lane + j * 32;
                float v = (Hs[r * Hn + c] - mu) * inv * g2[c] + be2[c];
                Hs[r * Hn + c] = 0.5f * v * (1.f + erff(v * 0.70710678118654752f));
            }
        }
    }
    __syncthreads();

    // split H to bf16 pair in smem
    for (int i = tid; i < 32 * 256; i += 256) {
        int r = i >> 8, c = i & 255;
        float f = Hs[r * Hn + c];
        __nv_bfloat16 h0 = __float2bfloat16(f);
        Hs0[r * DEC_LDH + c] = h0;
        Hs1[r * DEC_LDH + c] = __float2bfloat16(f - __bfloat162float(h0));
    }
    __syncthreads();

    // mma GEMM2: H[32x256] @ W4[256x512], 3 bf16 terms, fused err epilogue
    {
        const uint32_t h0b = smem_u32(Hs0);
        const uint32_t h1b = smem_u32(Hs1);
        uint32_t a0_addr[2], a1_addr[2];
#pragma unroll
        for (int mi = 0; mi < 2; ++mi) {
            uint32_t off = (uint32_t)((mi * 16 + (lane & 15)) * DEC_LDH * 2 + (lane >> 4) * 16);
            a0_addr[mi] = h0b + off;
            a1_addr[mi] = h1b + off;
        }

        float e_part[2][2] = {{0.f, 0.f}, {0.f, 0.f}};

#pragma unroll
        for (int h2 = 0; h2 < 2; ++h2) {
            float acc[2][4][4];
#pragma unroll
            for (int mi = 0; mi < 2; ++mi)
#pragma unroll
                for (int nj = 0; nj < 4; ++nj)
#pragma unroll
                    for (int k = 0; k < 4; ++k) acc[mi][nj][k] = 0.f;

            const int j0 = wid * 8 + h2 * 4;
            for (int s = 0; s < 16; ++s) {
                uint32_t a0[2][4], a1[2][4];
#pragma unroll
                for (int mi = 0; mi < 2; ++mi) {
                    ldsm_x4(a0[mi], a0_addr[mi] + s * 32);
                    ldsm_x4(a1[mi], a1_addr[mi] + s * 32);
                }
                uint32_t b0[4][2], b1[4][2];
#pragma unroll
                for (int nj = 0; nj < 4; ++nj) {
                    uint2 v = g_W4f[(size_t)(((s * 64 + j0 + nj) * 2 + 0) * 32 + lane)];
                    b0[nj][0] = v.x; b0[nj][1] = v.y;
                    uint2 w = g_W4f[(size_t)(((s * 64 + j0 + nj) * 2 + 1) * 32 + lane)];
                    b1[nj][0] = w.x; b1[nj][1] = w.y;
                }
#pragma unroll
                for (int mi = 0; mi < 2; ++mi)
#pragma unroll
                    for (int nj = 0; nj < 4; ++nj) {
                        mma_bf16(acc[mi][nj], a0[mi], b0[nj]);
                        mma_bf16(acc[mi][nj], a1[mi], b0[nj]);
                        mma_bf16(acc[mi][nj], a0[mi], b1[nj]);
                    }
            }

            // err contribution for this half's 32 cols
#pragma unroll
            for (int nj = 0; nj < 4; ++nj) {
                int col = wid * 64 + h2 * 32 + nj * 8 + (lane & 3) * 2;
                float2 bb = *(const float2*)(b4 + col);
#pragma unroll
                for (int mi = 0; mi < 2; ++mi) {
#pragma unroll
                    for (int hr = 0; hr < 2; ++hr) {
                        int rowg = row0 + mi * 16 + (lane >> 2) + hr * 8;
                        float2 xx = *(const float2*)(X + (size_t)rowg * Dn + col);
                        float d0 = acc[mi][nj][hr * 2]     + bb.x - xx.x;
                        float d1 = acc[mi][nj][hr * 2 + 1] + bb.y - xx.y;
                        e_part[mi][hr] += d0 * d0 + d1 * d1;
                    }
                }
            }
        }

        // reduce across lane&3 (same row), then across warps via smem
#pragma unroll
        for (int mi = 0; mi < 2; ++mi)
#pragma unroll
            for (int hr = 0; hr < 2; ++hr) {
                float v = e_part[mi][hr];
                v += __shfl_xor_sync(0xffffffff, v, 1);
                v += __shfl_xor_sync(0xffffffff, v, 2);
                if ((lane & 3) == 0)
                    ep[(mi * 16 + (lane >> 2) + hr * 8) * 8 + wid] = v;
            }
    }
    __syncthreads();
    if (tid < 32) {
        float s = 0.f;
#pragma unroll
        for (int w = 0; w < 8; ++w) s += ep[tid * 8 + w];
        g_err[row0 + tid] = s * (1.f / Dn);
    }
}

// ---------------- global mean ----------------
__global__ void reduce_kernel()
{
    __shared__ float s[256];
    int tid = threadIdx.x;
    float a = 0.f;
    for (int i = tid; i < Bn; i += 256) a += g_err[i];
    s[tid] = a;
    __syncthreads();
    for (int o = 128; o > 0; o >>= 1) {
        if (tid < o) s[tid] += s[tid + o];
        __syncthreads();
    }
    if (tid == 0) g_sum = s[0];
}

// ---------------- MDL + output ----------------
__global__ void final_kernel(float* __restrict__ out)
{
    int i = blockIdx.x * 256 + threadIdx.x;
    float scale = g_sum * (1.f / Bn) + 1e-8f;
    float err = g_err[i];
    float eb = (fabsf(err) / scale + logf(2.f * scale)) * 1.4426950408889634f;
    float tb = 14.f + eb;
    out[i]          = err;
    out[Bn + i]     = (Dn * 32.f) / tb;
    out[2 * Bn + i] = tb;
    out[3 * Bn + i] = (float)g_idx[i];
}

// ---------------- launch ----------------
extern "C" void kernel_launch(void* const* d_in, const int* in_sizes, int n_in,
                              void* d_out, int out_size)
{
    const float* X   = (const float*)d_in[0];
    const float* W1  = (const float*)d_in[1];
    const float* b1  = (const float*)d_in[2];
    const float* g1  = (const float*)d_in[3];
    const float* be1 = (const float*)d_in[4];
    const float* W2  = (const float*)d_in[5];
    const float* b2  = (const float*)d_in[6];
    const float* CB  = (const float*)d_in[7];
    const float* W3  = (const float*)d_in[8];
    const float* b3  = (const float*)d_in[9];
    const float* g2  = (const float*)d_in[10];
    const float* be2 = (const float*)d_in[11];
    const float* W4  = (const float*)d_in[12];
    const float* b4  = (const float*)d_in[13];
    float* out = (float*)d_out;

    cudaFuncSetAttribute(encoder_kernel,     cudaFuncAttributeMaxDynamicSharedMemorySize, 98304);
    cudaFuncSetAttribute(dist_coarse_kernel, cudaFuncAttributeMaxDynamicSharedMemorySize, DSM2_TOT);
    cudaFuncSetAttribute(decoder_kernel,     cudaFuncAttributeMaxDynamicSharedMemorySize, DEC_SMEM);

    c0split_kernel<<<Kn / 8, 256>>>(CB);
    w4split_kernel<<<256, 256>>>(W4);
    encoder_kernel<<<Bn / 32, 256, 98304>>>(X, W1, b1, g1, be1, W2, b2);
    enorm_kernel<<<Bn / 8, 256>>>();
    dist_coarse_kernel<<<Bn / 64, 256, DSM2_TOT>>>();
    rescore_kernel<<<Bn / 4, 128>>>(CB);
    decoder_kernel<<<Bn / 32, 256, DEC_SMEM>>>(CB, W3, b3, g2, be2, b4, X);
    reduce_kernel<<<1, 256>>>();
    final_kernel<<<Bn / 256, 256>>>(out);
}

// round 12
// speedup vs baseline: 1.4962x; 1.0633x over previous
#include <cuda_runtime.h>
#include <cuda_bf16.h>
#include <math.h>
#include <stdint.h>

#define Bn 16384
#define Dn 512
#define Kn 16384
#define Hn 256
#define Zn 128
#define LDK2 136                     // padded row stride in bf16 (272B); bytes 256..259 carry -0.5||c||^2

// ---------------- scratch ----------------
__device__ __align__(16) float g_enc[(size_t)Bn * Zn];
__device__ __align__(16) __nv_bfloat16 g_e0p[(size_t)Bn * LDK2];
__device__ __align__(16) __nv_bfloat16 g_c0p[(size_t)Kn * LDK2];
__device__ float g_negc2[Kn];
__device__ float g_en2[Bn];
__device__ float g_dn2[Bn];
__device__ float g_Rmax2;
__device__ float g_Nmax2;
__device__ float g_smax[Bn];
__device__ float g_cand_val[(size_t)Bn * 48];
__device__ int   g_cand_idx[(size_t)Bn * 48];
__device__ float g_fourth[(size_t)Bn * 16];
__device__ int   g_idx[Bn];
__device__ float g_err[Bn];
__device__ float g_sum;
// W4 pre-packed B-fragments: [s(16)][j(64)][p(2)][lane(32)] of uint2
__device__ __align__(16) uint2 g_W4f[16 * 64 * 2 * 32];

// ---------------- helpers ----------------
__device__ __forceinline__ uint32_t smem_u32(const void* p) {
    uint32_t a;
    asm("{ .reg .u64 t; cvta.to.shared.u64 t, %1; cvt.u32.u64 %0, t; }" : "=r"(a) : "l"(p));
    return a;
}
__device__ __forceinline__ void ldsm_x4(uint32_t r[4], uint32_t addr) {
    asm volatile("ldmatrix.sync.aligned.m8n8.x4.shared.b16 {%0,%1,%2,%3}, [%4];"
        : "=r"(r[0]), "=r"(r[1]), "=r"(r[2]), "=r"(r[3]) : "r"(addr));
}
__device__ __forceinline__ void mma_bf16(float d[4], const uint32_t a[4], const uint32_t b[2]) {
    asm volatile("mma.sync.aligned.m16n8k16.row.col.f32.bf16.bf16.f32 "
        "{%0,%1,%2,%3}, {%4,%5,%6,%7}, {%8,%9}, {%0,%1,%2,%3};"
        : "+f"(d[0]), "+f"(d[1]), "+f"(d[2]), "+f"(d[3])
        : "r"(a[0]), "r"(a[1]), "r"(a[2]), "r"(a[3]), "r"(b[0]), "r"(b[1]));
}
__device__ __forceinline__ uint32_t pack_bf16(float a, float b) {
    __nv_bfloat162 t = __floats2bfloat162_rn(a, b);
    return *(uint32_t*)&t;
}
// packed f32x2 helpers (PTX >= 8.6, sm_100+ base ISA)
__device__ __forceinline__ uint64_t packf2(float a, float b) {
    uint64_t r;
    asm("mov.b64 %0, {%1, %2};" : "=l"(r) : "f"(a), "f"(b));
    return r;
}
__device__ __forceinline__ void fma_f32x2(uint64_t& d, uint64_t a, uint64_t b) {
    asm("fma.rn.f32x2 %0, %1, %2, %0;" : "+l"(d) : "l"(a), "l"(b));
}
__device__ __forceinline__ void unpackf2(float& lo, float& hi, uint64_t v) {
    asm("mov.b64 {%0, %1}, %2;" : "=f"(lo), "=f"(hi) : "l"(v));
}
__device__ __forceinline__ void bulk_g2s(uint32_t dst, const void* src, uint32_t bytes, uint32_t mbar) {
    asm volatile("cp.async.bulk.shared::cluster.global.mbarrier::complete_tx::bytes [%0], [%1], %2, [%3];"
        :: "r"(dst), "l"(src), "r"(bytes), "r"(mbar) : "memory");
}
#define MBAR_INIT(mb, c) \
    asm volatile("mbarrier.init.shared.b64 [%0], %1;" :: "r"((uint32_t)(mb)), "r"((uint32_t)(c)) : "memory")
#define MBAR_EXPECT_TX(mb, n) \
    asm volatile("mbarrier.arrive.expect_tx.shared.b64 _, [%0], %1;" :: "r"((uint32_t)(mb)), "r"((uint32_t)(n)) : "memory")
#define MBAR_ARRIVE(mb) \
    asm volatile("mbarrier.arrive.shared.b64 _, [%0];" :: "r"((uint32_t)(mb)) : "memory")
#define MBAR_WAIT(mb, par) do { \
    uint32_t _m = (uint32_t)(mb); uint32_t _p = (uint32_t)(par); uint32_t _d; \
    asm volatile("{\n\t.reg .pred p;\n\t" \
        "mbarrier.try_wait.parity.acquire.cta.shared::cta.b64 p, [%1], %2;\n\t" \
        "selp.b32 %0, 1, 0, p;\n\t}" : "=r"(_d) : "r"(_m), "r"(_p) : "memory"); \
    if (!_d) { \
        asm volatile("{\n\t.reg .pred P1;\n\t" \
            "WL_%=:\n\t" \
            "mbarrier.try_wait.parity.acquire.cta.shared::cta.b64 P1, [%0], %1, 0x989680;\n\t" \
            "@P1 bra.uni WD_%=;\n\tbra.uni WL_%=;\n\tWD_%=:\n\t}" \
            :: "r"(_m), "r"(_p) : "memory"); \
    } } while (0)

// ---------------- encoder (f32x2 packed GEMMs; math identical to scalar version) ----------------
__global__ void encoder_kernel(const float* __restrict__ X,
                               const float* __restrict__ W1, const float* __restrict__ b1,
                               const float* __restrict__ g1, const float* __restrict__ be1,
                               const float* __restrict__ W2, const float* __restrict__ b2)
{
    extern __shared__ float sm[];
    float* Xs = sm;
    float* Hs = sm + 32 * Dn;
    const int tid = threadIdx.x;
    const int row0 = blockIdx.x * 32;

    {
        const float4* Xg = (const float4*)(X + (size_t)row0 * Dn);
        float4* Xs4 = (float4*)Xs;
        for (int i = tid; i < 32 * Dn / 4; i += 256) Xs4[i] = Xg[i];
    }
    __syncthreads();

    // GEMM1: thread -> cols (c, c+128), rows rbase..rbase+15, packed f32x2
    {
        const float4* Xs4 = (const float4*)Xs;
        const int c = tid & 127;
        const int rbase = (tid >> 7) * 16;
        uint64_t acc2[16];
#pragma unroll
        for (int r = 0; r < 16; ++r) acc2[r] = 0ull;
        for (int d = 0; d < Dn; d += 4) {
            uint64_t wp[4];
#pragma unroll
            for (int j = 0; j < 4; ++j)
                wp[j] = packf2(W1[(d + j) * Hn + c], W1[(d + j) * Hn + c + 128]);
#pragma unroll
            for (int r = 0; r < 16; ++r) {
                float4 x = Xs4[((rbase + r) * Dn + d) >> 2];
                fma_f32x2(acc2[r], packf2(x.x, x.x), wp[0]);
                fma_f32x2(acc2[r], packf2(x.y, x.y), wp[1]);
                fma_f32x2(acc2[r], packf2(x.z, x.z), wp[2]);
                fma_f32x2(acc2[r], packf2(x.w, x.w), wp[3]);
            }
        }
        float bba = b1[c], bbb = b1[c + 128];
#pragma unroll
        for (int r = 0; r < 16; ++r) {
            float lo, hi;
            unpackf2(lo, hi, acc2[r]);
            Hs[(rbase + r) * Hn + c]       = lo + bba;
            Hs[(rbase + r) * Hn + c + 128] = hi + bbb;
        }
    }
    __syncthreads();

    // LN + GELU (unchanged)
    {
        const int warp = tid >> 5, lane = tid & 31;
        for (int rr = 0; rr < 4; ++rr) {
            int r = warp + rr * 8;
            float s = 0.f, s2 = 0.f;
#pragma unroll
            for (int j = 0; j < 8; ++j) {
                float v = Hs[r * Hn + lane + j * 32];
                s += v; s2 += v * v;
            }
#pragma unroll
            for (int o = 16; o > 0; o >>= 1) {
                s  += __shfl_xor_sync(0xffffffff, s,  o);
                s2 += __shfl_xor_sync(0xffffffff, s2, o);
            }
            float mu  = s * (1.f / Hn);
            float var = s2 * (1.f / Hn) - mu * mu;
            float inv = rsqrtf(var + 1e-5f);
#pragma unroll
            for (int j = 0; j < 8; ++j) {
                int c = lane + j * 32;
                float v = (Hs[r * Hn + c] - mu) * inv * g1[c] + be1[c];
                Hs[r * Hn + c] = 0.5f * v * (1.f + erff(v * 0.70710678118654752f));
            }
        }
    }
    __syncthreads();

    // GEMM2: thread -> cols (c2, c2+64), rows rbase..rbase+7, packed f32x2
    {
        const float4* Hs4 = (const float4*)Hs;
        const int c2 = tid & 63;
        const int rbase = (tid >> 6) * 8;
        uint64_t acc2[8];
#pragma unroll
        for (int r = 0; r < 8; ++r) acc2[r] = 0ull;
        for (int d = 0; d < Hn; d += 4) {
            uint64_t wp[4];
#pragma unroll
            for (int j = 0; j < 4; ++j)
                wp[j] = packf2(W2[(d + j) * Zn + c2], W2[(d + j) * Zn + c2 + 64]);
#pragma unroll
            for (int r = 0; r < 8; ++r) {
                float4 h = Hs4[((rbase + r) * Hn + d) >> 2];
                fma_f32x2(acc2[r], packf2(h.x, h.x), wp[0]);
                fma_f32x2(acc2[r], packf2(h.y, h.y), wp[1]);
                fma_f32x2(acc2[r], packf2(h.z, h.z), wp[2]);
                fma_f32x2(acc2[r], packf2(h.w, h.w), wp[3]);
            }
        }
        float bba = b2[c2], bbb = b2[c2 + 64];
#pragma unroll
        for (int r = 0; r < 8; ++r) {
            float lo, hi;
            unpackf2(lo, hi, acc2[r]);
            g_enc[(size_t)(row0 + rbase + r) * Zn + c2]      = lo + bba;
            g_enc[(size_t)(row0 + rbase + r) * Zn + c2 + 64] = hi + bbb;
        }
    }
}

// ---------------- per-row e0 (padded) + norms ----------------
__global__ void enorm_kernel()
{
    int gw = (blockIdx.x * 256 + threadIdx.x) >> 5;
    int lane = threadIdx.x & 31;
    const float4 e4 = ((const float4*)(g_enc + (size_t)gw * 128))[lane];
    float e0x = __bfloat162float(__float2bfloat16(e4.x));
    float e0y = __bfloat162float(__float2bfloat16(e4.y));
    float e0z = __bfloat162float(__float2bfloat16(e4.z));
    float e0w = __bfloat162float(__float2bfloat16(e4.w));
    *(uint2*)(g_e0p + (size_t)gw * LDK2 + lane * 4) =
        make_uint2(pack_bf16(e4.x, e4.y), pack_bf16(e4.z, e4.w));
    float en2 = e4.x*e4.x + e4.y*e4.y + e4.z*e4.z + e4.w*e4.w;
    float dx = e4.x - e0x, dy = e4.y - e0y, dz = e4.z - e0z, dw = e4.w - e0w;
    float dn2 = dx*dx + dy*dy + dz*dz + dw*dw;
#pragma unroll
    for (int o = 16; o > 0; o >>= 1) {
        en2 += __shfl_xor_sync(0xffffffff, en2, o);
        dn2 += __shfl_xor_sync(0xffffffff, dn2, o);
    }
    if (lane == 0) { g_en2[gw] = en2; g_dn2[gw] = dn2; }
}

// ---------------- codebook prep (padded; nc stashed in row padding) ----------------
__global__ void c0split_kernel(const float* __restrict__ C)
{
    int code = (blockIdx.x * 256 + threadIdx.x) >> 5;
    int lane = threadIdx.x & 31;
    const float4 c4 = ((const float4*)(C + (size_t)code * 128))[lane];
    float c0x = __bfloat162float(__float2bfloat16(c4.x));
    float c0y = __bfloat162float(__float2bfloat16(c4.y));
    float c0z = __bfloat162float(__float2bfloat16(c4.z));
    float c0w = __bfloat162float(__float2bfloat16(c4.w));
    *(uint2*)(g_c0p + (size_t)code * LDK2 + lane * 4) =
        make_uint2(pack_bf16(c4.x, c4.y), pack_bf16(c4.z, c4.w));
    float c2 = c4.x*c4.x + c4.y*c4.y + c4.z*c4.z + c4.w*c4.w;
    float n2 = c0x*c0x + c0y*c0y + c0z*c0z + c0w*c0w;
    float dx = c4.x - c0x, dy = c4.y - c0y, dz = c4.z - c0z, dw = c4.w - c0w;
    float r2 = dx*dx + dy*dy + dz*dz + dw*dw;
#pragma unroll
    for (int o = 16; o > 0; o >>= 1) {
        c2 += __shfl_xor_sync(0xffffffff, c2, o);
        n2 += __shfl_xor_sync(0xffffffff, n2, o);
        r2 += __shfl_xor_sync(0xffffffff, r2, o);
    }
    if (lane == 0) {
        float nc = -0.5f * c2;
        g_negc2[code] = nc;
        *(float*)((char*)g_c0p + (size_t)code * (LDK2 * 2) + 256) = nc;
        atomicMax((int*)&g_Rmax2, __float_as_int(r2));
        atomicMax((int*)&g_Nmax2, __float_as_int(n2));
    }
}

// ---------------- W4 fragment pre-pack (2-way bf16 split, B-frag order) ----------------
__global__ void w4split_kernel(const float* __restrict__ W4)
{
    int i = blockIdx.x * 256 + threadIdx.x;
    int lane = i & 31;
    int p = (i >> 5) & 1;
    int j = (i >> 6) & 63;
    int s = i >> 12;
    int n = j * 8 + (lane >> 2);
    uint32_t regs[2];
#pragma unroll
    for (int r = 0; r < 2; ++r) {
        int k = s * 16 + (lane & 3) * 2 + r * 8;
        float wa = W4[(size_t)k * Dn + n];
        float wb = W4[(size_t)(k + 1) * Dn + n];
        float va, vb;
        if (p == 0) {
            va = __bfloat162float(__float2bfloat16(wa));
            vb = __bfloat162float(__float2bfloat16(wb));
        } else {
            va = wa - __bfloat162float(__float2bfloat16(wa));
            vb = wb - __bfloat162float(__float2bfloat16(wb));
        }
        regs[r] = pack_bf16(va, vb);
    }
    g_W4f[i] = make_uint2(regs[0], regs[1]);
}

// ---------------- coarse distance: mbarrier ring (unchanged from R10) ----------------
#define A_BYTES (64 * LDK2 * 2)
#define TILE_BYTES (128 * LDK2 * 2)
#define SB_A 0
#define SB_B0 A_BYTES
#define SB_MBAR (A_BYTES + 2 * TILE_BYTES)
#define SB_RED (SB_MBAR + 64)
#define DSM2_TOT (SB_RED + 64 * 16 * 4)

__global__ __launch_bounds__(256, 2) void dist_coarse_kernel()
{
    extern __shared__ char smem[];
    float* redsm = (float*)(smem + SB_RED);

    const int tid  = threadIdx.x;
    const int lane = tid & 31;
    const int wid  = tid >> 5;
    const int warp_m = wid >> 2;
    const int warp_n = wid & 3;
    const int row0 = blockIdx.x * 64;

    const uint32_t sbA    = smem_u32(smem) + SB_A;
    const uint32_t sbB0   = smem_u32(smem) + SB_B0;
    const uint32_t mbA    = smem_u32(smem) + SB_MBAR;
    const uint32_t mbF0   = mbA + 8;
    const uint32_t mbF1   = mbA + 16;
    const uint32_t mbE0   = mbA + 24;
    const uint32_t mbE1   = mbA + 32;

    if (tid == 0) {
        MBAR_INIT(mbA, 1);
        MBAR_INIT(mbF0, 1);
        MBAR_INIT(mbF1, 1);
        MBAR_INIT(mbE0, 8);
        MBAR_INIT(mbE1, 8);
    }
    __syncthreads();

    if (tid == 0) {
        MBAR_EXPECT_TX(mbA, A_BYTES);
        bulk_g2s(sbA, g_e0p + (size_t)row0 * LDK2, A_BYTES, mbA);
        MBAR_EXPECT_TX(mbF0, TILE_BYTES);
        bulk_g2s(sbB0, g_c0p, TILE_BYTES, mbF0);
    }

    uint32_t a_addr[2];
#pragma unroll
    for (int mi = 0; mi < 2; ++mi)
        a_addr[mi] = sbA + ((warp_m * 32 + mi * 16 + (lane & 15)) * LDK2 + (lane >> 4) * 8) * 2;
    uint32_t b_addr[2];
#pragma unroll
    for (int njp = 0; njp < 2; ++njp)
        b_addr[njp] = sbB0 + ((warp_n * 32 + njp * 16 + (lane & 7) + ((lane >> 4) << 3)) * LDK2
                              + ((lane >> 3) & 1) * 8) * 2;

    float v1[4], v2[4], v3[4], v4[4];
    int   i1[4], i2[4], i3[4];
#pragma unroll
    for (int r = 0; r < 4; ++r) {
        v1[r] = v2[r] = v3[r] = v4[r] = -INFINITY;
        i1[r] = i2[r] = i3[r] = 0;
    }

    const int cq = (lane & 3) * 2;

    MBAR_WAIT(mbA, 0);

    for (int t = 0, kt = 0; t < 128; ++t, kt += 128) {
        const uint32_t bufo = (uint32_t)(t & 1) * TILE_BYTES;

        if (tid == 0 && t < 127) {
            const int tn = t + 1;
            const int bn = tn & 1;
            const int f  = tn >> 1;
            uint32_t mbE = bn ? mbE1 : mbE0;
            uint32_t mbF = bn ? mbF1 : mbF0;
            if (f > 0) MBAR_WAIT(mbE, (f & 1) ^ 1);
            MBAR_EXPECT_TX(mbF, TILE_BYTES);
            bulk_g2s(sbB0 + (uint32_t)bn * TILE_BYTES,
                     g_c0p + (size_t)(kt + 128) * LDK2, TILE_BYTES, mbF);
        }

        MBAR_WAIT((t & 1) ? mbF1 : mbF0, (t >> 1) & 1);

        float nc[8];
#pragma unroll
        for (int nj = 0; nj < 4; ++nj) {
#pragma unroll
            for (int q = 0; q < 2; ++q) {
                asm volatile("ld.shared.f32 %0, [%1];"
                    : "=f"(nc[nj * 2 + q])
                    : "r"(sbB0 + bufo + (uint32_t)(warp_n * 32 + nj * 8 + cq + q) * (LDK2 * 2) + 256));
            }
        }

        float acc[2][4][4];
#pragma unroll
        for (int mi = 0; mi < 2; ++mi)
#pragma unroll
            for (int nj = 0; nj < 4; ++nj)
#pragma unroll
                for (int k = 0; k < 4; ++k) acc[mi][nj][k] = 0.f;

#pragma unroll
        for (int s = 0; s < 8; ++s) {
            uint32_t af[2][4], bf[2][4];
#pragma unroll
            for (int mi = 0; mi < 2; ++mi) ldsm_x4(af[mi], a_addr[mi] + s * 32);
#pragma unroll
            for (int njp = 0; njp < 2; ++njp) ldsm_x4(bf[njp], b_addr[njp] + bufo + s * 32);
#pragma unroll
            for (int mi = 0; mi < 2; ++mi)
#pragma unroll
                for (int nj = 0; nj < 4; ++nj)
                    mma_bf16(acc[mi][nj], af[mi], bf[nj >> 1] + (nj & 1) * 2);
        }

        if (lane == 0) MBAR_ARRIVE((t & 1) ? mbE1 : mbE0);

#pragma unroll
        for (int mi = 0; mi < 2; ++mi) {
#pragma unroll
            for (int h = 0; h < 2; ++h) {
                const int ri = mi * 2 + h;
                float s0 = acc[mi][0][h * 2]     + nc[0];
                float s1 = acc[mi][0][h * 2 + 1] + nc[1];
                float s2 = acc[mi][1][h * 2]     + nc[2];
                float s3 = acc[mi][1][h * 2 + 1] + nc[3];
                float s4 = acc[mi][2][h * 2]     + nc[4];
                float s5 = acc[mi][2][h * 2 + 1] + nc[5];
                float s6 = acc[mi][3][h * 2]     + nc[6];
                float s7 = acc[mi][3][h * 2 + 1] + nc[7];
                float m8 = fmaxf(fmaxf(fmaxf(s0, s1), fmaxf(s2, s3)),
                                 fmaxf(fmaxf(s4, s5), fmaxf(s6, s7)));
                if (m8 > v4[ri]) {
                    float sv[8] = {s0, s1, s2, s3, s4, s5, s6, s7};
#pragma unroll
                    for (int j = 0; j < 8; ++j) {
                        float v = sv[j];
                        if (v > v4[ri]) {
                            int idx = kt + warp_n * 32 + (j >> 1) * 8 + cq + (j & 1);
                            if (v > v1[ri]) {
                                v4[ri] = v3[ri]; v3[ri] = v2[ri]; i3[ri] = i2[ri];
                                v2[ri] = v1[ri]; i2[ri] = i1[ri];
                                v1[ri] = v; i1[ri] = idx;
                            } else if (v > v2[ri]) {
                                v4[ri] = v3[ri]; v3[ri] = v2[ri]; i3[ri] = i2[ri];
                                v2[ri] = v; i2[ri] = idx;
                            } else if (v > v3[ri]) {
                                v4[ri] = v3[ri]; v3[ri] = v; i3[ri] = idx;
                            } else {
                                v4[ri] = v;
                            }
                        }
                    }
                }
            }
        }
    }

    const int slot = warp_n * 4 + (lane & 3);
#pragma unroll
    for (int ri = 0; ri < 4; ++ri) {
        int mi = ri >> 1, h = ri & 1;
        int lrow = warp_m * 32 + mi * 16 + (lane >> 2) + h * 8;
        size_t row = (size_t)(row0 + lrow);
        g_cand_val[row * 48 + slot * 3]     = v1[ri];
        g_cand_idx[row * 48 + slot * 3]     = i1[ri];
        g_cand_val[row * 48 + slot * 3 + 1] = v2[ri];
        g_cand_idx[row * 48 + slot * 3 + 1] = i2[ri];
        g_cand_val[row * 48 + slot * 3 + 2] = v3[ri];
        g_cand_idx[row * 48 + slot * 3 + 2] = i3[ri];
        g_fourth[row * 16 + slot] = v4[ri];
        redsm[lrow * 16 + slot] = v1[ri];
    }
    __syncthreads();
    if (tid < 64) {
        float m = redsm[tid * 16];
#pragma unroll
        for (int w = 1; w < 16; ++w) m = fmaxf(m, redsm[tid * 16 + w]);
        g_smax[row0 + tid] = m;
    }
}

// ---------------- exact rescore (warp per row) ----------------
__global__ void rescore_kernel(const float* __restrict__ CB)
{
    const int r = blockIdx.x * 4 + (threadIdx.x >> 5);
    const int lane = threadIdx.x & 31;

    float delta = sqrtf(g_en2[r]) * sqrtf(g_Rmax2) + sqrtf(g_dn2[r]) * sqrtf(g_Nmax2);
    float thresh = g_smax[r] - 1.05f * delta - 1e-4f;

    float th = (lane < 16) ? g_fourth[(size_t)r * 16 + lane] : -INFINITY;
    bool flag = __ballot_sync(0xffffffff, th >= thresh) != 0;

    const float4 e4 = ((const float4*)(g_enc + (size_t)r * 128))[lane];

    float bs = -INFINITY;
    int bi = 0x7fffffff;

    if (!flag) {
        for (int s = 0; s < 48; ++s) {
            float v = g_cand_val[(size_t)r * 48 + s];
            if (v >= thresh) {
                int idx = g_cand_idx[(size_t)r * 48 + s];
                float4 c4 = ((const float4*)(CB + (size_t)idx * 128))[lane];
                float d = e4.x*c4.x + e4.y*c4.y + e4.z*c4.z + e4.w*c4.w;
#pragma unroll
                for (int o = 16; o > 0; o >>= 1) d += __shfl_xor_sync(0xffffffff, d, o);
                float sx = d + g_negc2[idx];
                if (sx > bs || (sx == bs && idx < bi)) { bs = sx; bi = idx; }
            }
        }
    } else {
        for (int k = 0; k < Kn; ++k) {
            float4 c4 = ((const float4*)(CB + (size_t)k * 128))[lane];
            float d = e4.x*c4.x + e4.y*c4.y + e4.z*c4.z + e4.w*c4.w;
#pragma unroll
            for (int o = 16; o > 0; o >>= 1) d += __shfl_xor_sync(0xffffffff, d, o);
            float sx = d + g_negc2[k];
            if (sx > bs) { bs = sx; bi = k; }
        }
    }
    if (lane == 0) g_idx[r] = bi;
}

// ---------------- decoder (unchanged from R11) ----------------
#define DEC_HS0_OFF (32 * Zn + 32 * Hn)
#define DEC_LDH 264
#define DEC_SMEM (12288 * 4 + 2 * 32 * DEC_LDH * 2 + 32 * 8 * 4)

__global__ void decoder_kernel(const float* __restrict__ C,
                               const float* __restrict__ W3, const float* __restrict__ b3,
                               const float* __restrict__ g2, const float* __restrict__ be2,
                               const float* __restrict__ b4,
                               const float* __restrict__ X)
{
    extern __shared__ float sm[];
    float* Qs = sm;
    float* Hs = sm + 32 * Zn;
    __nv_bfloat16* Hs0 = (__nv_bfloat16*)(sm + DEC_HS0_OFF);
    __nv_bfloat16* Hs1 = Hs0 + 32 * DEC_LDH;
    float* ep = (float*)(Hs1 + 32 * DEC_LDH);
    const int tid = threadIdx.x;
    const int lane = tid & 31;
    const int wid = tid >> 5;
    const int row0 = blockIdx.x * 32;

    for (int i = tid; i < 32 * 32; i += 256) {
        int r = i >> 5, d4 = i & 31;
        int code = g_idx[row0 + r];
        ((float4*)Qs)[r * 32 + d4] = ((const float4*)C)[(size_t)code * 32 + d4];
    }
    __syncthreads();

    {
        const float4* Qs4 = (const float4*)Qs;
        float acc[32];
#pragma unroll
        for (int r = 0; r < 32; ++r) acc[r] = 0.f;
        const int col = tid;
        for (int d = 0; d < Zn; d += 4) {
            float w0 = W3[(d + 0) * Hn + col];
            float w1 = W3[(d + 1) * Hn + col];
            float w2 = W3[(d + 2) * Hn + col];
            float w3 = W3[(d + 3) * Hn + col];
#pragma unroll
            for (int r = 0; r < 32; ++r) {
                float4 q = Qs4[(r * Zn + d) >> 2];
                acc[r] = fmaf(q.x, w0, acc[r]);
                acc[r] = fmaf(q.y, w1, acc[r]);
                acc[r] = fmaf(q.z, w2, acc[r]);
                acc[r] = fmaf(q.w, w3, acc[r]);
            }
        }
        float bb = b3[col];
#pragma unroll
        for (int r = 0; r < 32; ++r) Hs[r * Hn + col] = acc[r] + bb;
    }
    __syncthreads();

    {
        for (int rr = 0; rr < 4; ++rr) {
            int r = wid + rr * 8;
            float s = 0.f, s2 = 0.f;
#pragma unroll
            for (int j = 0; j < 8; ++j) {
                float v = Hs[r * Hn + lane + j * 32];
                s += v; s2 += v * v;
            }
#pragma unroll
            for (int o = 16; o > 0; o >>= 1) {
                s  += __shfl_xor_sync(0xffffffff, s,  o);
                s2 += __shfl_xor_sync(0xffffffff, s2, o);
            }
            float mu  = s * (1.f / Hn);
            float var = s2 * (1.f / Hn) - mu * mu;
            float inv = rsqrtf(var + 1e-5f);
#pragma unroll
            for (int j = 0; j < 8; ++j) {
                int c = lane + j * 32;
                float v = (Hs[r * Hn + c] - mu) * inv * g2[c] + be2[c];
                Hs[r * Hn + c] = 0.5f * v * (1.f + erff(v * 0.70710678118654752f));
            }
        }
    }
    __syncthreads();

    for (int i = tid; i < 32 * 256; i += 256) {
        int r = i >> 8, c = i & 255;
        float f = Hs[r * Hn + c];
        __nv_bfloat16 h0 = __float2bfloat16(f);
        Hs0[r * DEC_LDH + c] = h0;
        Hs1[r * DEC_LDH + c] = __float2bfloat16(f - __bfloat162float(h0));
    }
    __syncthreads();

    {
        const uint32_t h0b = smem_u32(Hs0);
        const uint32_t h1b = smem_u32(Hs1);
        uint32_t a0_addr[2], a1_addr[2];
#pragma unroll
        for (int mi = 0; mi < 2; ++mi) {
            uint32_t off = (uint32_t)((mi * 16 + (lane & 15)) * DEC_LDH * 2 + (lane >> 4) * 16);
            a0_addr[mi] = h0b + off;
            a1_addr[mi] = h1b + off;
        }

        float e_part[2][2] = {{0.f, 0.f}, {0.f, 0.f}};

#pragma unroll
        for (int h2 = 0; h2 < 2; ++h2) {
            float acc[2][4][4];
#pragma unroll
            for (int mi = 0; mi < 2; ++mi)
#pragma unroll
                for (int nj = 0; nj < 4; ++nj)
#pragma unroll
                    for (int k = 0; k < 4; ++k) acc[mi][nj][k] = 0.f;

            const int j0 = wid * 8 + h2 * 4;
            for (int s = 0; s < 16; ++s) {
                uint32_t a0[2][4], a1[2][4];
#pragma unroll
                for (int mi = 0; mi < 2; ++mi) {
                    ldsm_x4(a0[mi], a0_addr[mi] + s * 32);
                    ldsm_x4(a1[mi], a1_addr[mi] + s * 32);
                }
                uint32_t b0[4][2], b1[4][2];
#pragma unroll
                for (int nj = 0; nj < 4; ++nj) {
                    uint2 v = g_W4f[(size_t)(((s * 64 + j0 + nj) * 2 + 0) * 32 + lane)];
                    b0[nj][0] = v.x; b0[nj][1] = v.y;
                    uint2 w = g_W4f[(size_t)(((s * 64 + j0 + nj) * 2 + 1) * 32 + lane)];
                    b1[nj][0] = w.x; b1[nj][1] = w.y;
                }
#pragma unroll
                for (int mi = 0; mi < 2; ++mi)
#pragma unroll
                    for (int nj = 0; nj < 4; ++nj) {
                        mma_bf16(acc[mi][nj], a0[mi], b0[nj]);
                        mma_bf16(acc[mi][nj], a1[mi], b0[nj]);
                        mma_bf16(acc[mi][nj], a0[mi], b1[nj]);
                    }
            }

#pragma unroll
            for (int nj = 0; nj < 4; ++nj) {
                int col = wid * 64 + h2 * 32 + nj * 8 + (lane & 3) * 2;
                float2 bb = *(const float2*)(b4 + col);
#pragma unroll
                for (int mi = 0; mi < 2; ++mi) {
#pragma unroll
                    for (int hr = 0; hr < 2; ++hr) {
                        int rowg = row0 + mi * 16 + (lane >> 2) + hr * 8;
                        float2 xx = *(const float2*)(X + (size_t)rowg * Dn + col);
                        float d0 = acc[mi][nj][hr * 2]     + bb.x - xx.x;
                        float d1 = acc[mi][nj][hr * 2 + 1] + bb.y - xx.y;
                        e_part[mi][hr] += d0 * d0 + d1 * d1;
                    }
                }
            }
        }

#pragma unroll
        for (int mi = 0; mi < 2; ++mi)
#pragma unroll
            for (int hr = 0; hr < 2; ++hr) {
                float v = e_part[mi][hr];
                v += __shfl_xor_sync(0xffffffff, v, 1);
                v += __shfl_xor_sync(0xffffffff, v, 2);
                if ((lane & 3) == 0)
                    ep[(mi * 16 + (lane >> 2) + hr * 8) * 8 + wid] = v;
            }
    }
    __syncthreads();
    if (tid < 32) {
        float s = 0.f;
#pragma unroll
        for (int w = 0; w < 8; ++w) s += ep[tid * 8 + w];
        g_err[row0 + tid] = s * (1.f / Dn);
    }
}

// ---------------- global mean ----------------
__global__ void reduce_kernel()
{
    __shared__ float s[256];
    int tid = threadIdx.x;
    float a = 0.f;
    for (int i = tid; i < Bn; i += 256) a += g_err[i];
    s[tid] = a;
    __syncthreads();
    for (int o = 128; o > 0; o >>= 1) {
        if (tid < o) s[tid] += s[tid + o];
        __syncthreads();
    }
    if (tid == 0) g_sum = s[0];
}

// ---------------- MDL + output ----------------
__global__ void final_kernel(float* __restrict__ out)
{
    int i = blockIdx.x * 256 + threadIdx.x;
    float scale = g_sum * (1.f / Bn) + 1e-8f;
    float err = g_err[i];
    float eb = (fabsf(err) / scale + logf(2.f * scale)) * 1.4426950408889634f;
    float tb = 14.f + eb;
    out[i]          = err;
    out[Bn + i]     = (Dn * 32.f) / tb;
    out[2 * Bn + i] = tb;
    out[3 * Bn + i] = (float)g_idx[i];
}

// ---------------- launch ----------------
extern "C" void kernel_launch(void* const* d_in, const int* in_sizes, int n_in,
                              void* d_out, int out_size)
{
    const float* X   = (const float*)d_in[0];
    const float* W1  = (const float*)d_in[1];
    const float* b1  = (const float*)d_in[2];
    const float* g1  = (const float*)d_in[3];
    const float* be1 = (const float*)d_in[4];
    const float* W2  = (const float*)d_in[5];
    const float* b2  = (const float*)d_in[6];
    const float* CB  = (const float*)d_in[7];
    const float* W3  = (const float*)d_in[8];
    const float* b3  = (const float*)d_in[9];
    const float* g2  = (const float*)d_in[10];
    const float* be2 = (const float*)d_in[11];
    const float* W4  = (const float*)d_in[12];
    const float* b4  = (const float*)d_in[13];
    float* out = (float*)d_out;

    cudaFuncSetAttribute(encoder_kernel,     cudaFuncAttributeMaxDynamicSharedMemorySize, 98304);
    cudaFuncSetAttribute(dist_coarse_kernel, cudaFuncAttributeMaxDynamicSharedMemorySize, DSM2_TOT);
    cudaFuncSetAttribute(decoder_kernel,     cudaFuncAttributeMaxDynamicSharedMemorySize, DEC_SMEM);

    c0split_kernel<<<Kn / 8, 256>>>(CB);
    w4split_kernel<<<256, 256>>>(W4);
    encoder_kernel<<<Bn / 32, 256, 98304>>>(X, W1, b1, g1, be1, W2, b2);
    enorm_kernel<<<Bn / 8, 256>>>();
    dist_coarse_kernel<<<Bn / 64, 256, DSM2_TOT>>>();
    rescore_kernel<<<Bn / 4, 128>>>(CB);
    decoder_kernel<<<Bn / 32, 256, DEC_SMEM>>>(CB, W3, b3, g2, be2, b4, X);
    reduce_kernel<<<1, 256>>>();
    final_kernel<<<Bn / 256, 256>>>(out);
}

// round 13
// speedup vs baseline: 1.5381x; 1.0280x over previous
#include <cuda_runtime.h>
#include <cuda_bf16.h>
#include <math.h>
#include <stdint.h>

#define Bn 16384
#define Dn 512
#define Kn 16384
#define Hn 256
#define Zn 128
#define LDK2 136                     // padded row stride in bf16 (272B); bytes 256..259 carry -0.5||c||^2

// ---------------- scratch ----------------
__device__ __align__(16) float g_enc[(size_t)Bn * Zn];
__device__ __align__(16) __nv_bfloat16 g_e0p[(size_t)Bn * LDK2];
__device__ __align__(16) __nv_bfloat16 g_c0p[(size_t)Kn * LDK2];
__device__ float g_negc2[Kn];
__device__ float g_en2[Bn];
__device__ float g_dn2[Bn];
__device__ float g_Rmax2;
__device__ float g_Nmax2;
__device__ float g_smax[Bn];
__device__ float g_cand_val[(size_t)Bn * 48];
__device__ int   g_cand_idx[(size_t)Bn * 48];
__device__ float g_fourth[(size_t)Bn * 16];
__device__ int   g_idx[Bn];
__device__ float g_err[Bn];
__device__ float g_sum;
// W4 pre-packed B-fragments: [s(16)][j(64)][p(2)][lane(32)] of uint2
__device__ __align__(16) uint2 g_W4f[16 * 64 * 2 * 32];

// ---------------- helpers ----------------
__device__ __forceinline__ uint32_t smem_u32(const void* p) {
    uint32_t a;
    asm("{ .reg .u64 t; cvta.to.shared.u64 t, %1; cvt.u32.u64 %0, t; }" : "=r"(a) : "l"(p));
    return a;
}
__device__ __forceinline__ void ldsm_x4(uint32_t r[4], uint32_t addr) {
    asm volatile("ldmatrix.sync.aligned.m8n8.x4.shared.b16 {%0,%1,%2,%3}, [%4];"
        : "=r"(r[0]), "=r"(r[1]), "=r"(r[2]), "=r"(r[3]) : "r"(addr));
}
__device__ __forceinline__ void mma_bf16(float d[4], const uint32_t a[4], const uint32_t b[2]) {
    asm volatile("mma.sync.aligned.m16n8k16.row.col.f32.bf16.bf16.f32 "
        "{%0,%1,%2,%3}, {%4,%5,%6,%7}, {%8,%9}, {%0,%1,%2,%3};"
        : "+f"(d[0]), "+f"(d[1]), "+f"(d[2]), "+f"(d[3])
        : "r"(a[0]), "r"(a[1]), "r"(a[2]), "r"(a[3]), "r"(b[0]), "r"(b[1]));
}
__device__ __forceinline__ uint32_t pack_bf16(float a, float b) {
    __nv_bfloat162 t = __floats2bfloat162_rn(a, b);
    return *(uint32_t*)&t;
}
// packed f32x2 helpers (PTX >= 8.6, sm_100+ base ISA)
__device__ __forceinline__ uint64_t packf2(float a, float b) {
    uint64_t r;
    asm("mov.b64 %0, {%1, %2};" : "=l"(r) : "f"(a), "f"(b));
    return r;
}
__device__ __forceinline__ void fma_f32x2(uint64_t& d, uint64_t a, uint64_t b) {
    asm("fma.rn.f32x2 %0, %1, %2, %0;" : "+l"(d) : "l"(a), "l"(b));
}
__device__ __forceinline__ void unpackf2(float& lo, float& hi, uint64_t v) {
    asm("mov.b64 {%0, %1}, %2;" : "=f"(lo), "=f"(hi) : "l"(v));
}
__device__ __forceinline__ void bulk_g2s(uint32_t dst, const void* src, uint32_t bytes, uint32_t mbar) {
    asm volatile("cp.async.bulk.shared::cluster.global.mbarrier::complete_tx::bytes [%0], [%1], %2, [%3];"
        :: "r"(dst), "l"(src), "r"(bytes), "r"(mbar) : "memory");
}
#define MBAR_INIT(mb, c) \
    asm volatile("mbarrier.init.shared.b64 [%0], %1;" :: "r"((uint32_t)(mb)), "r"((uint32_t)(c)) : "memory")
#define MBAR_EXPECT_TX(mb, n) \
    asm volatile("mbarrier.arrive.expect_tx.shared.b64 _, [%0], %1;" :: "r"((uint32_t)(mb)), "r"((uint32_t)(n)) : "memory")
#define MBAR_ARRIVE(mb) \
    asm volatile("mbarrier.arrive.shared.b64 _, [%0];" :: "r"((uint32_t)(mb)) : "memory")
#define MBAR_WAIT(mb, par) do { \
    uint32_t _m = (uint32_t)(mb); uint32_t _p = (uint32_t)(par); uint32_t _d; \
    asm volatile("{\n\t.reg .pred p;\n\t" \
        "mbarrier.try_wait.parity.acquire.cta.shared::cta.b64 p, [%1], %2;\n\t" \
        "selp.b32 %0, 1, 0, p;\n\t}" : "=r"(_d) : "r"(_m), "r"(_p) : "memory"); \
    if (!_d) { \
        asm volatile("{\n\t.reg .pred P1;\n\t" \
            "WL_%=:\n\t" \
            "mbarrier.try_wait.parity.acquire.cta.shared::cta.b64 P1, [%0], %1, 0x989680;\n\t" \
            "@P1 bra.uni WD_%=;\n\tbra.uni WL_%=;\n\tWD_%=:\n\t}" \
            :: "r"(_m), "r"(_p) : "memory"); \
    } } while (0)

// ---------------- encoder (f32x2 packed GEMMs) ----------------
__global__ void encoder_kernel(const float* __restrict__ X,
                               const float* __restrict__ W1, const float* __restrict__ b1,
                               const float* __restrict__ g1, const float* __restrict__ be1,
                               const float* __restrict__ W2, const float* __restrict__ b2)
{
    extern __shared__ float sm[];
    float* Xs = sm;
    float* Hs = sm + 32 * Dn;
    const int tid = threadIdx.x;
    const int row0 = blockIdx.x * 32;

    {
        const float4* Xg = (const float4*)(X + (size_t)row0 * Dn);
        float4* Xs4 = (float4*)Xs;
        for (int i = tid; i < 32 * Dn / 4; i += 256) Xs4[i] = Xg[i];
    }
    __syncthreads();

    // GEMM1: thread -> cols (c, c+128), rows rbase..rbase+15, packed f32x2
    {
        const float4* Xs4 = (const float4*)Xs;
        const int c = tid & 127;
        const int rbase = (tid >> 7) * 16;
        uint64_t acc2[16];
#pragma unroll
        for (int r = 0; r < 16; ++r) acc2[r] = 0ull;
        for (int d = 0; d < Dn; d += 4) {
            uint64_t wp[4];
#pragma unroll
            for (int j = 0; j < 4; ++j)
                wp[j] = packf2(W1[(d + j) * Hn + c], W1[(d + j) * Hn + c + 128]);
#pragma unroll
            for (int r = 0; r < 16; ++r) {
                float4 x = Xs4[((rbase + r) * Dn + d) >> 2];
                fma_f32x2(acc2[r], packf2(x.x, x.x), wp[0]);
                fma_f32x2(acc2[r], packf2(x.y, x.y), wp[1]);
                fma_f32x2(acc2[r], packf2(x.z, x.z), wp[2]);
                fma_f32x2(acc2[r], packf2(x.w, x.w), wp[3]);
            }
        }
        float bba = b1[c], bbb = b1[c + 128];
#pragma unroll
        for (int r = 0; r < 16; ++r) {
            float lo, hi;
            unpackf2(lo, hi, acc2[r]);
            Hs[(rbase + r) * Hn + c]       = lo + bba;
            Hs[(rbase + r) * Hn + c + 128] = hi + bbb;
        }
    }
    __syncthreads();

    // LN + GELU
    {
        const int warp = tid >> 5, lane = tid & 31;
        for (int rr = 0; rr < 4; ++rr) {
            int r = warp + rr * 8;
            float s = 0.f, s2 = 0.f;
#pragma unroll
            for (int j = 0; j < 8; ++j) {
                float v = Hs[r * Hn + lane + j * 32];
                s += v; s2 += v * v;
            }
#pragma unroll
            for (int o = 16; o > 0; o >>= 1) {
                s  += __shfl_xor_sync(0xffffffff, s,  o);
                s2 += __shfl_xor_sync(0xffffffff, s2, o);
            }
            float mu  = s * (1.f / Hn);
            float var = s2 * (1.f / Hn) - mu * mu;
            float inv = rsqrtf(var + 1e-5f);
#pragma unroll
            for (int j = 0; j < 8; ++j) {
                int c = lane + j * 32;
                float v = (Hs[r * Hn + c] - mu) * inv * g1[c] + be1[c];
                Hs[r * Hn + c] = 0.5f * v * (1.f + erff(v * 0.70710678118654752f));
            }
        }
    }
    __syncthreads();

    // GEMM2: thread -> cols (c2, c2+64), rows rbase..rbase+7, packed f32x2
    {
        const float4* Hs4 = (const float4*)Hs;
        const int c2 = tid & 63;
        const int rbase = (tid >> 6) * 8;
        uint64_t acc2[8];
#pragma unroll
        for (int r = 0; r < 8; ++r) acc2[r] = 0ull;
        for (int d = 0; d < Hn; d += 4) {
            uint64_t wp[4];
#pragma unroll
            for (int j = 0; j < 4; ++j)
                wp[j] = packf2(W2[(d + j) * Zn + c2], W2[(d + j) * Zn + c2 + 64]);
#pragma unroll
            for (int r = 0; r < 8; ++r) {
                float4 h = Hs4[((rbase + r) * Hn + d) >> 2];
                fma_f32x2(acc2[r], packf2(h.x, h.x), wp[0]);
                fma_f32x2(acc2[r], packf2(h.y, h.y), wp[1]);
                fma_f32x2(acc2[r], packf2(h.z, h.z), wp[2]);
                fma_f32x2(acc2[r], packf2(h.w, h.w), wp[3]);
            }
        }
        float bba = b2[c2], bbb = b2[c2 + 64];
#pragma unroll
        for (int r = 0; r < 8; ++r) {
            float lo, hi;
            unpackf2(lo, hi, acc2[r]);
            g_enc[(size_t)(row0 + rbase + r) * Zn + c2]      = lo + bba;
            g_enc[(size_t)(row0 + rbase + r) * Zn + c2 + 64] = hi + bbb;
        }
    }
}

// ---------------- per-row e0 (padded) + norms ----------------
__global__ void enorm_kernel()
{
    int gw = (blockIdx.x * 256 + threadIdx.x) >> 5;
    int lane = threadIdx.x & 31;
    const float4 e4 = ((const float4*)(g_enc + (size_t)gw * 128))[lane];
    float e0x = __bfloat162float(__float2bfloat16(e4.x));
    float e0y = __bfloat162float(__float2bfloat16(e4.y));
    float e0z = __bfloat162float(__float2bfloat16(e4.z));
    float e0w = __bfloat162float(__float2bfloat16(e4.w));
    *(uint2*)(g_e0p + (size_t)gw * LDK2 + lane * 4) =
        make_uint2(pack_bf16(e4.x, e4.y), pack_bf16(e4.z, e4.w));
    float en2 = e4.x*e4.x + e4.y*e4.y + e4.z*e4.z + e4.w*e4.w;
    float dx = e4.x - e0x, dy = e4.y - e0y, dz = e4.z - e0z, dw = e4.w - e0w;
    float dn2 = dx*dx + dy*dy + dz*dz + dw*dw;
#pragma unroll
    for (int o = 16; o > 0; o >>= 1) {
        en2 += __shfl_xor_sync(0xffffffff, en2, o);
        dn2 += __shfl_xor_sync(0xffffffff, dn2, o);
    }
    if (lane == 0) { g_en2[gw] = en2; g_dn2[gw] = dn2; }
}

// ---------------- codebook prep (padded; nc stashed in row padding) ----------------
__global__ void c0split_kernel(const float* __restrict__ C)
{
    int code = (blockIdx.x * 256 + threadIdx.x) >> 5;
    int lane = threadIdx.x & 31;
    const float4 c4 = ((const float4*)(C + (size_t)code * 128))[lane];
    float c0x = __bfloat162float(__float2bfloat16(c4.x));
    float c0y = __bfloat162float(__float2bfloat16(c4.y));
    float c0z = __bfloat162float(__float2bfloat16(c4.z));
    float c0w = __bfloat162float(__float2bfloat16(c4.w));
    *(uint2*)(g_c0p + (size_t)code * LDK2 + lane * 4) =
        make_uint2(pack_bf16(c4.x, c4.y), pack_bf16(c4.z, c4.w));
    float c2 = c4.x*c4.x + c4.y*c4.y + c4.z*c4.z + c4.w*c4.w;
    float n2 = c0x*c0x + c0y*c0y + c0z*c0z + c0w*c0w;
    float dx = c4.x - c0x, dy = c4.y - c0y, dz = c4.z - c0z, dw = c4.w - c0w;
    float r2 = dx*dx + dy*dy + dz*dz + dw*dw;
#pragma unroll
    for (int o = 16; o > 0; o >>= 1) {
        c2 += __shfl_xor_sync(0xffffffff, c2, o);
        n2 += __shfl_xor_sync(0xffffffff, n2, o);
        r2 += __shfl_xor_sync(0xffffffff, r2, o);
    }
    if (lane == 0) {
        float nc = -0.5f * c2;
        g_negc2[code] = nc;
        *(float*)((char*)g_c0p + (size_t)code * (LDK2 * 2) + 256) = nc;
        atomicMax((int*)&g_Rmax2, __float_as_int(r2));
        atomicMax((int*)&g_Nmax2, __float_as_int(n2));
    }
}

// ---------------- W4 fragment pre-pack (2-way bf16 split, B-frag order) ----------------
__global__ void w4split_kernel(const float* __restrict__ W4)
{
    int i = blockIdx.x * 256 + threadIdx.x;
    int lane = i & 31;
    int p = (i >> 5) & 1;
    int j = (i >> 6) & 63;
    int s = i >> 12;
    int n = j * 8 + (lane >> 2);
    uint32_t regs[2];
#pragma unroll
    for (int r = 0; r < 2; ++r) {
        int k = s * 16 + (lane & 3) * 2 + r * 8;
        float wa = W4[(size_t)k * Dn + n];
        float wb = W4[(size_t)(k + 1) * Dn + n];
        float va, vb;
        if (p == 0) {
            va = __bfloat162float(__float2bfloat16(wa));
            vb = __bfloat162float(__float2bfloat16(wb));
        } else {
            va = wa - __bfloat162float(__float2bfloat16(wa));
            vb = wb - __bfloat162float(__float2bfloat16(wb));
        }
        regs[r] = pack_bf16(va, vb);
    }
    g_W4f[i] = make_uint2(regs[0], regs[1]);
}

// ---------------- coarse distance: mbarrier ring; nc folded into acc init ----------------
#define A_BYTES (64 * LDK2 * 2)
#define TILE_BYTES (128 * LDK2 * 2)
#define SB_A 0
#define SB_B0 A_BYTES
#define SB_MBAR (A_BYTES + 2 * TILE_BYTES)
#define SB_RED (SB_MBAR + 64)
#define DSM2_TOT (SB_RED + 64 * 16 * 4)

__global__ __launch_bounds__(256, 2) void dist_coarse_kernel()
{
    extern __shared__ char smem[];
    float* redsm = (float*)(smem + SB_RED);

    const int tid  = threadIdx.x;
    const int lane = tid & 31;
    const int wid  = tid >> 5;
    const int warp_m = wid >> 2;
    const int warp_n = wid & 3;
    const int row0 = blockIdx.x * 64;

    const uint32_t sbA    = smem_u32(smem) + SB_A;
    const uint32_t sbB0   = smem_u32(smem) + SB_B0;
    const uint32_t mbA    = smem_u32(smem) + SB_MBAR;
    const uint32_t mbF0   = mbA + 8;
    const uint32_t mbF1   = mbA + 16;
    const uint32_t mbE0   = mbA + 24;
    const uint32_t mbE1   = mbA + 32;

    if (tid == 0) {
        MBAR_INIT(mbA, 1);
        MBAR_INIT(mbF0, 1);
        MBAR_INIT(mbF1, 1);
        MBAR_INIT(mbE0, 8);
        MBAR_INIT(mbE1, 8);
    }
    __syncthreads();

    if (tid == 0) {
        MBAR_EXPECT_TX(mbA, A_BYTES);
        bulk_g2s(sbA, g_e0p + (size_t)row0 * LDK2, A_BYTES, mbA);
        MBAR_EXPECT_TX(mbF0, TILE_BYTES);
        bulk_g2s(sbB0, g_c0p, TILE_BYTES, mbF0);
    }

    uint32_t a_addr[2];
#pragma unroll
    for (int mi = 0; mi < 2; ++mi)
        a_addr[mi] = sbA + ((warp_m * 32 + mi * 16 + (lane & 15)) * LDK2 + (lane >> 4) * 8) * 2;
    uint32_t b_addr[2];
#pragma unroll
    for (int njp = 0; njp < 2; ++njp)
        b_addr[njp] = sbB0 + ((warp_n * 32 + njp * 16 + (lane & 7) + ((lane >> 4) << 3)) * LDK2
                              + ((lane >> 3) & 1) * 8) * 2;

    float v1[4], v2[4], v3[4], v4[4];
    int   i1[4], i2[4], i3[4];
#pragma unroll
    for (int r = 0; r < 4; ++r) {
        v1[r] = v2[r] = v3[r] = v4[r] = -INFINITY;
        i1[r] = i2[r] = i3[r] = 0;
    }

    const int cq = (lane & 3) * 2;

    MBAR_WAIT(mbA, 0);

    for (int t = 0, kt = 0; t < 128; ++t, kt += 128) {
        const uint32_t bufo = (uint32_t)(t & 1) * TILE_BYTES;

        if (tid == 0 && t < 127) {
            const int tn = t + 1;
            const int bn = tn & 1;
            const int f  = tn >> 1;
            uint32_t mbE = bn ? mbE1 : mbE0;
            uint32_t mbF = bn ? mbF1 : mbF0;
            if (f > 0) MBAR_WAIT(mbE, (f & 1) ^ 1);
            MBAR_EXPECT_TX(mbF, TILE_BYTES);
            bulk_g2s(sbB0 + (uint32_t)bn * TILE_BYTES,
                     g_c0p + (size_t)(kt + 128) * LDK2, TILE_BYTES, mbF);
        }

        MBAR_WAIT((t & 1) ? mbF1 : mbF0, (t >> 1) & 1);

        // nc from smem row padding (broadcast LDS)
        float nc[8];
#pragma unroll
        for (int nj = 0; nj < 4; ++nj) {
#pragma unroll
            for (int q = 0; q < 2; ++q) {
                asm volatile("ld.shared.f32 %0, [%1];"
                    : "=f"(nc[nj * 2 + q])
                    : "r"(sbB0 + bufo + (uint32_t)(warp_n * 32 + nj * 8 + cq + q) * (LDK2 * 2) + 256));
            }
        }

        // accumulators initialized with -0.5||c||^2 (D = A.B + D); no epilogue FADD needed
        float acc[2][4][4];
#pragma unroll
        for (int mi = 0; mi < 2; ++mi)
#pragma unroll
            for (int nj = 0; nj < 4; ++nj)
#pragma unroll
                for (int k = 0; k < 4; ++k) acc[mi][nj][k] = nc[nj * 2 + (k & 1)];

#pragma unroll
        for (int s = 0; s < 8; ++s) {
            uint32_t af[2][4], bf[2][4];
#pragma unroll
            for (int mi = 0; mi < 2; ++mi) ldsm_x4(af[mi], a_addr[mi] + s * 32);
#pragma unroll
            for (int njp = 0; njp < 2; ++njp) ldsm_x4(bf[njp], b_addr[njp] + bufo + s * 32);
#pragma unroll
            for (int mi = 0; mi < 2; ++mi)
#pragma unroll
                for (int nj = 0; nj < 4; ++nj)
                    mma_bf16(acc[mi][nj], af[mi], bf[nj >> 1] + (nj & 1) * 2);
        }

        if (lane == 0) MBAR_ARRIVE((t & 1) ? mbE1 : mbE0);

        // epilogue: raw acc already holds scores; max-of-8 quick reject, rare insert
#pragma unroll
        for (int mi = 0; mi < 2; ++mi) {
#pragma unroll
            for (int h = 0; h < 2; ++h) {
                const int ri = mi * 2 + h;
                float s0 = acc[mi][0][h * 2];
                float s1 = acc[mi][0][h * 2 + 1];
                float s2 = acc[mi][1][h * 2];
                float s3 = acc[mi][1][h * 2 + 1];
                float s4 = acc[mi][2][h * 2];
                float s5 = acc[mi][2][h * 2 + 1];
                float s6 = acc[mi][3][h * 2];
                float s7 = acc[mi][3][h * 2 + 1];
                float m8 = fmaxf(fmaxf(fmaxf(s0, s1), fmaxf(s2, s3)),
                                 fmaxf(fmaxf(s4, s5), fmaxf(s6, s7)));
                if (m8 > v4[ri]) {
                    float sv[8] = {s0, s1, s2, s3, s4, s5, s6, s7};
#pragma unroll
                    for (int j = 0; j < 8; ++j) {
                        float v = sv[j];
                        if (v > v4[ri]) {
                            int idx = kt + warp_n * 32 + (j >> 1) * 8 + cq + (j & 1);
                            if (v > v1[ri]) {
                                v4[ri] = v3[ri]; v3[ri] = v2[ri]; i3[ri] = i2[ri];
                                v2[ri] = v1[ri]; i2[ri] = i1[ri];
                                v1[ri] = v; i1[ri] = idx;
                            } else if (v > v2[ri]) {
                                v4[ri] = v3[ri]; v3[ri] = v2[ri]; i3[ri] = i2[ri];
                                v2[ri] = v; i2[ri] = idx;
                            } else if (v > v3[ri]) {
                                v4[ri] = v3[ri]; v3[ri] = v; i3[ri] = idx;
                            } else {
                                v4[ri] = v;
                            }
                        }
                    }
                }
            }
        }
    }

    const int slot = warp_n * 4 + (lane & 3);
#pragma unroll
    for (int ri = 0; ri < 4; ++ri) {
        int mi = ri >> 1, h = ri & 1;
        int lrow = warp_m * 32 + mi * 16 + (lane >> 2) + h * 8;
        size_t row = (size_t)(row0 + lrow);
        g_cand_val[row * 48 + slot * 3]     = v1[ri];
        g_cand_idx[row * 48 + slot * 3]     = i1[ri];
        g_cand_val[row * 48 + slot * 3 + 1] = v2[ri];
        g_cand_idx[row * 48 + slot * 3 + 1] = i2[ri];
        g_cand_val[row * 48 + slot * 3 + 2] = v3[ri];
        g_cand_idx[row * 48 + slot * 3 + 2] = i3[ri];
        g_fourth[row * 16 + slot] = v4[ri];
        redsm[lrow * 16 + slot] = v1[ri];
    }
    __syncthreads();
    if (tid < 64) {
        float m = redsm[tid * 16];
#pragma unroll
        for (int w = 1; w < 16; ++w) m = fmaxf(m, redsm[tid * 16 + w]);
        g_smax[row0 + tid] = m;
    }
}

// ---------------- exact rescore (warp per row) ----------------
__global__ void rescore_kernel(const float* __restrict__ CB)
{
    const int r = blockIdx.x * 4 + (threadIdx.x >> 5);
    const int lane = threadIdx.x & 31;

    float delta = sqrtf(g_en2[r]) * sqrtf(g_Rmax2) + sqrtf(g_dn2[r]) * sqrtf(g_Nmax2);
    float thresh = g_smax[r] - 1.05f * delta - 1e-4f;

    float th = (lane < 16) ? g_fourth[(size_t)r * 16 + lane] : -INFINITY;
    bool flag = __ballot_sync(0xffffffff, th >= thresh) != 0;

    const float4 e4 = ((const float4*)(g_enc + (size_t)r * 128))[lane];

    float bs = -INFINITY;
    int bi = 0x7fffffff;

    if (!flag) {
        for (int s = 0; s < 48; ++s) {
            float v = g_cand_val[(size_t)r * 48 + s];
            if (v >= thresh) {
                int idx = g_cand_idx[(size_t)r * 48 + s];
                float4 c4 = ((const float4*)(CB + (size_t)idx * 128))[lane];
                float d = e4.x*c4.x + e4.y*c4.y + e4.z*c4.z + e4.w*c4.w;
#pragma unroll
                for (int o = 16; o > 0; o >>= 1) d += __shfl_xor_sync(0xffffffff, d, o);
                float sx = d + g_negc2[idx];
                if (sx > bs || (sx == bs && idx < bi)) { bs = sx; bi = idx; }
            }
        }
    } else {
        for (int k = 0; k < Kn; ++k) {
            float4 c4 = ((const float4*)(CB + (size_t)k * 128))[lane];
            float d = e4.x*c4.x + e4.y*c4.y + e4.z*c4.z + e4.w*c4.w;
#pragma unroll
            for (int o = 16; o > 0; o >>= 1) d += __shfl_xor_sync(0xffffffff, d, o);
            float sx = d + g_negc2[k];
            if (sx > bs) { bs = sx; bi = k; }
        }
    }
    if (lane == 0) g_idx[r] = bi;
}

// ---------------- decoder: f32x2 GEMM1, mma GEMM2 ----------------
#define DEC_HS0_OFF (32 * Zn + 32 * Hn)
#define DEC_LDH 264
#define DEC_SMEM (12288 * 4 + 2 * 32 * DEC_LDH * 2 + 32 * 8 * 4)

__global__ void decoder_kernel(const float* __restrict__ C,
                               const float* __restrict__ W3, const float* __restrict__ b3,
                               const float* __restrict__ g2, const float* __restrict__ be2,
                               const float* __restrict__ b4,
                               const float* __restrict__ X)
{
    extern __shared__ float sm[];
    float* Qs = sm;
    float* Hs = sm + 32 * Zn;
    __nv_bfloat16* Hs0 = (__nv_bfloat16*)(sm + DEC_HS0_OFF);
    __nv_bfloat16* Hs1 = Hs0 + 32 * DEC_LDH;
    float* ep = (float*)(Hs1 + 32 * DEC_LDH);
    const int tid = threadIdx.x;
    const int lane = tid & 31;
    const int wid = tid >> 5;
    const int row0 = blockIdx.x * 32;

    for (int i = tid; i < 32 * 32; i += 256) {
        int r = i >> 5, d4 = i & 31;
        int code = g_idx[row0 + r];
        ((float4*)Qs)[r * 32 + d4] = ((const float4*)C)[(size_t)code * 32 + d4];
    }
    __syncthreads();

    // f32x2 GEMM1: thread -> cols (c, c+128), rows rbase..rbase+15
    {
        const float4* Qs4 = (const float4*)Qs;
        const int c = tid & 127;
        const int rbase = (tid >> 7) * 16;
        uint64_t acc2[16];
#pragma unroll
        for (int r = 0; r < 16; ++r) acc2[r] = 0ull;
        for (int d = 0; d < Zn; d += 4) {
            uint64_t wp[4];
#pragma unroll
            for (int j = 0; j < 4; ++j)
                wp[j] = packf2(W3[(d + j) * Hn + c], W3[(d + j) * Hn + c + 128]);
#pragma unroll
            for (int r = 0; r < 16; ++r) {
                float4 q = Qs4[((rbase + r) * Zn + d) >> 2];
                fma_f32x2(acc2[r], packf2(q.x, q.x), wp[0]);
                fma_f32x2(acc2[r], packf2(q.y, q.y), wp[1]);
                fma_f32x2(acc2[r], packf2(q.z, q.z), wp[2]);
                fma_f32x2(acc2[r], packf2(q.w, q.w), wp[3]);
            }
        }
        float bba = b3[c], bbb = b3[c + 128];
#pragma unroll
        for (int r = 0; r < 16; ++r) {
            float lo, hi;
            unpackf2(lo, hi, acc2[r]);
            Hs[(rbase + r) * Hn + c]       = lo + bba;
            Hs[(rbase + r) * Hn + c + 128] = hi + bbb;
        }
    }
    __syncthreads();

    {
        for (int rr = 0; rr < 4; ++rr) {
            int r = wid + rr * 8;
            float s = 0.f, s2 = 0.f;
#pragma unroll
            for (int j = 0; j < 8; ++j) {
                float v = Hs[r * Hn + lane + j * 32];
                s += v; s2 += v * v;
            }
#pragma unroll
            for (int o = 16; o > 0; o >>= 1) {
                s  += __shfl_xor_sync(0xffffffff, s,  o);
                s2 += __shfl_xor_sync(0xffffffff, s2, o);
            }
            float mu  = s * (1.f / Hn);
            float var = s2 * (1.f / Hn) - mu * mu;
            float inv = rsqrtf(var + 1e-5f);
#pragma unroll
            for (int j = 0; j < 8; ++j) {
                int c = lane + j * 32;
                float v = (Hs[r * Hn + c] - mu) * inv * g2[c] + be2[c];
                Hs[r * Hn + c] = 0.5f * v * (1.f + erff(v * 0.70710678118654752f));
            }
        }
    }
    __syncthreads();

    for (int i = tid; i < 32 * 256; i += 256) {
        int r = i >> 8, c = i & 255;
        float f = Hs[r * Hn + c];
        __nv_bfloat16 h0 = __float2bfloat16(f);
        Hs0[r * DEC_LDH + c] = h0;
        Hs1[r * DEC_LDH + c] = __float2bfloat16(f - __bfloat162float(h0));
    }
    __syncthreads();

    {
        const uint32_t h0b = smem_u32(Hs0);
        const uint32_t h1b = smem_u32(Hs1);
        uint32_t a0_addr[2], a1_addr[2];
#pragma unroll
        for (int mi = 0; mi < 2; ++mi) {
            uint32_t off = (uint32_t)((mi * 16 + (lane & 15)) * DEC_LDH * 2 + (lane >> 4) * 16);
            a0_addr[mi] = h0b + off;
            a1_addr[mi] = h1b + off;
        }

        float e_part[2][2] = {{0.f, 0.f}, {0.f, 0.f}};

#pragma unroll
        for (int h2 = 0; h2 < 2; ++h2) {
            float acc[2][4][4];
#pragma unroll
            for (int mi = 0; mi < 2; ++mi)
#pragma unroll
                for (int nj = 0; nj < 4; ++nj)
#pragma unroll
                    for (int k = 0; k < 4; ++k) acc[mi][nj][k] = 0.f;

            const int j0 = wid * 8 + h2 * 4;
            for (int s = 0; s < 16; ++s) {
                uint32_t a0[2][4], a1[2][4];
#pragma unroll
                for (int mi = 0; mi < 2; ++mi) {
                    ldsm_x4(a0[mi], a0_addr[mi] + s * 32);
                    ldsm_x4(a1[mi], a1_addr[mi] + s * 32);
                }
                uint32_t b0[4][2], b1[4][2];
#pragma unroll
                for (int nj = 0; nj < 4; ++nj) {
                    uint2 v = g_W4f[(size_t)(((s * 64 + j0 + nj) * 2 + 0) * 32 + lane)];
                    b0[nj][0] = v.x; b0[nj][1] = v.y;
                    uint2 w = g_W4f[(size_t)(((s * 64 + j0 + nj) * 2 + 1) * 32 + lane)];
                    b1[nj][0] = w.x; b1[nj][1] = w.y;
                }
#pragma unroll
                for (int mi = 0; mi < 2; ++mi)
#pragma unroll
                    for (int nj = 0; nj < 4; ++nj) {
                        mma_bf16(acc[mi][nj], a0[mi], b0[nj]);
                        mma_bf16(acc[mi][nj], a1[mi], b0[nj]);
                        mma_bf16(acc[mi][nj], a0[mi], b1[nj]);
                    }
            }

#pragma unroll
            for (int nj = 0; nj < 4; ++nj) {
                int col = wid * 64 + h2 * 32 + nj * 8 + (lane & 3) * 2;
                float2 bb = *(const float2*)(b4 + col);
#pragma unroll
                for (int mi = 0; mi < 2; ++mi) {
#pragma unroll
                    for (int hr = 0; hr < 2; ++hr) {
                        int rowg = row0 + mi * 16 + (lane >> 2) + hr * 8;
                        float2 xx = *(const float2*)(X + (size_t)rowg * Dn + col);
                        float d0 = acc[mi][nj][hr * 2]     + bb.x - xx.x;
                        float d1 = acc[mi][nj][hr * 2 + 1] + bb.y - xx.y;
                        e_part[mi][hr] += d0 * d0 + d1 * d1;
                    }
                }
            }
        }

#pragma unroll
        for (int mi = 0; mi < 2; ++mi)
#pragma unroll
            for (int hr = 0; hr < 2; ++hr) {
                float v = e_part[mi][hr];
                v += __shfl_xor_sync(0xffffffff, v, 1);
                v += __shfl_xor_sync(0xffffffff, v, 2);
                if ((lane & 3) == 0)
                    ep[(mi * 16 + (lane >> 2) + hr * 8) * 8 + wid] = v;
            }
    }
    __syncthreads();
    if (tid < 32) {
        float s = 0.f;
#pragma unroll
        for (int w = 0; w < 8; ++w) s += ep[tid * 8 + w];
        g_err[row0 + tid] = s * (1.f / Dn);
    }
}

// ---------------- global mean ----------------
__global__ void reduce_kernel()
{
    __shared__ float s[256];
    int tid = threadIdx.x;
    float a = 0.f;
    for (int i = tid; i < Bn; i += 256) a += g_err[i];
    s[tid] = a;
    __syncthreads();
    for (int o = 128; o > 0; o >>= 1) {
        if (tid < o) s[tid] += s[tid + o];
        __syncthreads();
    }
    if (tid == 0) g_sum = s[0];
}

// ---------------- MDL + output ----------------
__global__ void final_kernel(float* __restrict__ out)
{
    int i = blockIdx.x * 256 + threadIdx.x;
    float scale = g_sum * (1.f / Bn) + 1e-8f;
    float err = g_err[i];
    float eb = (fabsf(err) / scale + logf(2.f * scale)) * 1.4426950408889634f;
    float tb = 14.f + eb;
    out[i]          = err;
    out[Bn + i]     = (Dn * 32.f) / tb;
    out[2 * Bn + i] = tb;
    out[3 * Bn + i] = (float)g_idx[i];
}

// ---------------- launch ----------------
extern "C" void kernel_launch(void* const* d_in, const int* in_sizes, int n_in,
                              void* d_out, int out_size)
{
    const float* X   = (const float*)d_in[0];
    const float* W1  = (const float*)d_in[1];
    const float* b1  = (const float*)d_in[2];
    const float* g1  = (const float*)d_in[3];
    const float* be1 = (const float*)d_in[4];
    const float* W2  = (const float*)d_in[5];
    const float* b2  = (const float*)d_in[6];
    const float* CB  = (const float*)d_in[7];
    const float* W3  = (const float*)d_in[8];
    const float* b3  = (const float*)d_in[9];
    const float* g2  = (const float*)d_in[10];
    const float* be2 = (const float*)d_in[11];
    const float* W4  = (const float*)d_in[12];
    const float* b4  = (const float*)d_in[13];
    float* out = (float*)d_out;

    cudaFuncSetAttribute(encoder_kernel,     cudaFuncAttributeMaxDynamicSharedMemorySize, 98304);
    cudaFuncSetAttribute(dist_coarse_kernel, cudaFuncAttributeMaxDynamicSharedMemorySize, DSM2_TOT);
    cudaFuncSetAttribute(decoder_kernel,     cudaFuncAttributeMaxDynamicSharedMemorySize, DEC_SMEM);

    c0split_kernel<<<Kn / 8, 256>>>(CB);
    w4split_kernel<<<256, 256>>>(W4);
    encoder_kernel<<<Bn / 32, 256, 98304>>>(X, W1, b1, g1, be1, W2, b2);
    enorm_kernel<<<Bn / 8, 256>>>();
    dist_coarse_kernel<<<Bn / 64, 256, DSM2_TOT>>>();
    rescore_kernel<<<Bn / 4, 128>>>(CB);
    decoder_kernel<<<Bn / 32, 256, DEC_SMEM>>>(CB, W3, b3, g2, be2, b4, X);
    reduce_kernel<<<1, 256>>>();
    final_kernel<<<Bn / 256, 256>>>(out);
}